// round 9
// baseline (speedup 1.0000x reference)
#include <cuda_runtime.h>
#include <cuda_bf16.h>

#define Bsz 64
#define Lsz 500
#define Dsz 300
#define Fsz 100
#define IDs 32
#define BL  (Bsz*Lsz)   // 32000
#define KP  320         // padded K (and padded N) for the doc GEMM
#define NK  20          // KP / 16 k-iterations
#define KA  112         // padded F for the attention GEMM (7 x 16)

// ---------------- scratch (static device globals; no allocation) ----------------
__device__ __align__(16) __nv_bfloat16 g_Ah[2][BL*KP];    // A hi split (gathered emb, ungated)
__device__ __align__(16) __nv_bfloat16 g_Al[2][BL*KP];    // A lo split
__device__ __align__(16) __nv_bfloat16 g_Wh[2][KP*KP];    // B hi split, layout [n][k]
__device__ __align__(16) __nv_bfloat16 g_Wl[2][KP*KP];    // B lo split
__device__ float g_dots[2][BL*3];
__device__ float g_C[2][BL*300];
__device__ float g_ut[2][BL*Fsz];
__device__ __align__(16) __nv_bfloat16 g_uth[2][BL*KA];
__device__ __align__(16) __nv_bfloat16 g_utl[2][BL*KA];
__device__ float g_nrm[2][BL];
__device__ float g_att[2][BL];

__device__ __forceinline__ float warpSum(float v) {
#pragma unroll
    for (int o = 16; o; o >>= 1) v += __shfl_down_sync(0xffffffffu, v, o);
    return v;
}

__device__ __forceinline__ unsigned pack_bf(float x0, float x1, float& r0, float& r1) {
    __nv_bfloat16 h0 = __float2bfloat16(x0);
    __nv_bfloat16 h1 = __float2bfloat16(x1);
    r0 = x0 - __bfloat162float(h0);
    r1 = x1 - __bfloat162float(h1);
    return (unsigned)__bfloat16_as_ushort(h0) | ((unsigned)__bfloat16_as_ushort(h1) << 16);
}

__device__ __forceinline__ void ldsm4(unsigned& r0, unsigned& r1,
                                      unsigned& r2, unsigned& r3, unsigned addr) {
    asm volatile("ldmatrix.sync.aligned.m8n8.x4.shared.b16 {%0,%1,%2,%3}, [%4];"
                 : "=r"(r0), "=r"(r1), "=r"(r2), "=r"(r3) : "r"(addr));
}

__device__ __forceinline__ void mma_bf16(float* c, const unsigned* a, const unsigned* b) {
    asm volatile(
        "mma.sync.aligned.m16n8k16.row.col.f32.bf16.bf16.f32 "
        "{%0,%1,%2,%3}, {%4,%5,%6,%7}, {%8,%9}, {%0,%1,%2,%3};\n"
        : "+f"(c[0]), "+f"(c[1]), "+f"(c[2]), "+f"(c[3])
        : "r"(a[0]), "r"(a[1]), "r"(a[2]), "r"(a[3]), "r"(b[0]), "r"(b[1]));
}

__device__ __forceinline__ void cp16(unsigned sdst, const void* gsrc) {
    asm volatile("cp.async.cg.shared.global [%0], [%1], 16;" :: "r"(sdst), "l"(gsrc));
}
__device__ __forceinline__ void cp16z(unsigned sdst, const void* gsrc, bool v) {
    int sz = v ? 16 : 0;
    asm volatile("cp.async.cg.shared.global [%0], [%1], 16, %2;" :: "r"(sdst), "l"(gsrc), "r"(sz));
}
__device__ __forceinline__ void cp_commit() { asm volatile("cp.async.commit_group;"); }
template <int N>
__device__ __forceinline__ void cp_wait() { asm volatile("cp.async.wait_group %0;" :: "n"(N)); }

__device__ __forceinline__ unsigned s2u(const void* p) {
    unsigned a;
    asm("{ .reg .u64 t; cvta.to.shared.u64 t, %1; cvt.u32.u64 %0, t; }" : "=r"(a) : "l"(p));
    return a;
}

// ---------------- K0: repack + bf16-split doc-conv weights -> [n][k] padded ----------------
__global__ void k_prep(const float* __restrict__ uw, const float* __restrict__ iw) {
    int idx = blockIdx.x * 256 + threadIdx.x;
    if (idx >= 2 * KP * KP) return;
    int side = idx / (KP * KP);
    int r = idx - side * KP * KP;
    int n = r / KP, k = r % KP;
    float x = 0.f;
    if (n < 300 && k < 300) {
        int f = n % Fsz, ks = n / Fsz;
        const float* w = side ? iw : uw;
        x = w[(f * 3 + ks) * Dsz + k];
    }
    __nv_bfloat16 h = __float2bfloat16(x);
    float lo = x - __bfloat162float(h);
    g_Wh[side][n * KP + k] = h;
    g_Wl[side][n * KP + k] = __float2bfloat16(lo);
}

// ---------------- K1: gather + word-gate dots + bf16 hi/lo split (ungated) ----------------
__global__ void k_gather(const int* __restrict__ udoc, const int* __restrict__ idoc,
                         const float* __restrict__ uemb, const float* __restrict__ iemb,
                         const float* __restrict__ wc) {
    int side = blockIdx.y;
    int bl = blockIdx.x;
    const int* doc = side ? idoc : udoc;
    const float* emb = side ? iemb : uemb;
    int row = doc[bl];
    const float* e = emb + (size_t)row * Dsz;
    unsigned* ah = reinterpret_cast<unsigned*>(&g_Ah[side][(size_t)bl * KP]);
    unsigned* al = reinterpret_cast<unsigned*>(&g_Al[side][(size_t)bl * KP]);
    float p0 = 0.f, p1 = 0.f, p2 = 0.f;
    for (int p = threadIdx.x; p < KP / 2; p += 128) {
        int d = 2 * p;
        float x0 = 0.f, x1 = 0.f;
        if (d < 300) {
            float2 v = *reinterpret_cast<const float2*>(&e[d]);
            x0 = v.x; x1 = v.y;
            p0 += x0 * wc[d]       + x1 * wc[d + 1];
            p1 += x0 * wc[300 + d] + x1 * wc[301 + d];
            p2 += x0 * wc[600 + d] + x1 * wc[601 + d];
        }
        float l0, l1;
        unsigned hp = pack_bf(x0, x1, l0, l1);
        __nv_bfloat16 lb0 = __float2bfloat16(l0);
        __nv_bfloat16 lb1 = __float2bfloat16(l1);
        ah[p] = hp;
        al[p] = (unsigned)__bfloat16_as_ushort(lb0) | ((unsigned)__bfloat16_as_ushort(lb1) << 16);
    }
    __shared__ float sh[3][4];
    p0 = warpSum(p0); p1 = warpSum(p1); p2 = warpSum(p2);
    int lane = threadIdx.x & 31, w = threadIdx.x >> 5;
    if (lane == 0) { sh[0][w] = p0; sh[1][w] = p1; sh[2][w] = p2; }
    __syncthreads();
    if (threadIdx.x == 0) {
        g_dots[side][bl * 3 + 0] = sh[0][0] + sh[0][1] + sh[0][2] + sh[0][3];
        g_dots[side][bl * 3 + 1] = sh[1][0] + sh[1][1] + sh[1][2] + sh[1][3];
        g_dots[side][bl * 3 + 2] = sh[2][0] + sh[2][1] + sh[2][2] + sh[2][3];
    }
}

// ---------------- K3: bf16 mma GEMM (32000x320)@(320x320), 3-term split ----------------
// BM=128, BN=64, BK=16, 256 threads (8 warps 4x2), warp tile 32x32.
// 4-stage cp.async pipeline, one __syncthreads per iter, 3 CTAs/SM.
// mma phased (hi*hi -> hi*lo -> lo*hi) to cap register pressure at <=85.
__global__ __launch_bounds__(256, 3) void k_gemm_bf16() {
    const int side = blockIdx.z;
    float* __restrict__ Cm = g_C[side];

    extern __shared__ __align__(16) unsigned char smbuf[];   // 4 x 18432

    const int tid = threadIdx.x;
    const int lane = tid & 31, wid = tid >> 5;
    const int wm = wid >> 1, wn = wid & 1;
    const int n0 = blockIdx.x * 64;
    const int m0 = blockIdx.y * 128;

    const unsigned smem0 = s2u(&smbuf[0]);

    const int arow = tid >> 1, ahalf = tid & 1;
    const char* gA_h = (const char*)&g_Ah[side][((size_t)(m0 + arow)) * KP + ahalf * 8];
    const char* gA_l = (const char*)&g_Al[side][((size_t)(m0 + arow)) * KP + ahalf * 8];
    const unsigned sA_h = smem0 + arow * 48 + ahalf * 16;
    const unsigned sA_l = sA_h + 6144;
    const int brow = (tid & 127) >> 1;
    const __nv_bfloat16* gBarr = (tid < 128) ? g_Wh[side] : g_Wl[side];
    const char* gB = (const char*)&gBarr[((size_t)(n0 + brow)) * KP + ahalf * 8];
    const unsigned sB = smem0 + ((tid < 128) ? 12288u : 15360u) + brow * 48 + ahalf * 16;

    float acc[2][4][4];
#pragma unroll
    for (int i = 0; i < 2; i++)
#pragma unroll
        for (int j = 0; j < 4; j++)
#pragma unroll
            for (int q = 0; q < 4; q++) acc[i][j][q] = 0.f;

#pragma unroll
    for (int s = 0; s < 3; s++) {
        cp16(sA_h + s * 18432u, gA_h + s * 32);
        cp16(sA_l + s * 18432u, gA_l + s * 32);
        cp16(sB   + s * 18432u, gB   + s * 32);
        cp_commit();
    }

    const int l4 = lane & 7, g4 = lane >> 3;
    unsigned aoff[2];
#pragma unroll
    for (int mt = 0; mt < 2; mt++) {
        int rowm = wm * 32 + mt * 16 + (g4 & 1) * 8 + l4;
        int koff = (g4 >> 1) * 8;
        aoff[mt] = smem0 + (rowm * 24 + koff) * 2;
    }
    unsigned boff[2];
#pragma unroll
    for (int ntp = 0; ntp < 2; ntp++) {
        int rown = wn * 32 + ntp * 16 + (g4 >> 1) * 8 + l4;
        int koff = (g4 & 1) * 8;
        boff[ntp] = smem0 + 12288 + (rown * 24 + koff) * 2;
    }

    for (int it = 0; it < NK; it++) {
        const unsigned sbase = (unsigned)(it & 3) * 18432u;
        if (it < NK - 3) cp_wait<2>(); else cp_wait<0>();
        __syncthreads();

        if (it + 3 < NK) {
            const unsigned nb = (unsigned)((it + 3) & 3) * 18432u;
            cp16(sA_h + nb, gA_h + (it + 3) * 32);
            cp16(sA_l + nb, gA_l + (it + 3) * 32);
            cp16(sB   + nb, gB   + (it + 3) * 32);
            cp_commit();
        }

        // phase 1: hi*hi   (a_h, b_h live)
        unsigned a_h[2][4], b_h[2][4];
#pragma unroll
        for (int mt = 0; mt < 2; mt++)
            ldsm4(a_h[mt][0], a_h[mt][1], a_h[mt][2], a_h[mt][3], aoff[mt] + sbase);
#pragma unroll
        for (int ntp = 0; ntp < 2; ntp++)
            ldsm4(b_h[ntp][0], b_h[ntp][1], b_h[ntp][2], b_h[ntp][3], boff[ntp] + sbase);
#pragma unroll
        for (int mt = 0; mt < 2; mt++)
#pragma unroll
            for (int nt = 0; nt < 4; nt++)
                mma_bf16(acc[mt][nt], a_h[mt], &b_h[nt >> 1][(nt & 1) * 2]);

        // phase 2: hi*lo   (b_l replaces nothing yet; a_h still live)
        {
            unsigned b_l[2][4];
#pragma unroll
            for (int ntp = 0; ntp < 2; ntp++)
                ldsm4(b_l[ntp][0], b_l[ntp][1], b_l[ntp][2], b_l[ntp][3], boff[ntp] + sbase + 3072);
#pragma unroll
            for (int mt = 0; mt < 2; mt++)
#pragma unroll
                for (int nt = 0; nt < 4; nt++)
                    mma_bf16(acc[mt][nt], a_h[mt], &b_l[nt >> 1][(nt & 1) * 2]);
        }

        // phase 3: lo*hi   (a_l replaces a_h; b_h still live)
        {
            unsigned a_l[2][4];
#pragma unroll
            for (int mt = 0; mt < 2; mt++)
                ldsm4(a_l[mt][0], a_l[mt][1], a_l[mt][2], a_l[mt][3], aoff[mt] + sbase + 6144);
#pragma unroll
            for (int mt = 0; mt < 2; mt++)
#pragma unroll
                for (int nt = 0; nt < 4; nt++)
                    mma_bf16(acc[mt][nt], a_l[mt], &b_h[nt >> 1][(nt & 1) * 2]);
        }
    }

    // epilogue
#pragma unroll
    for (int mt = 0; mt < 2; mt++) {
        int r = m0 + wm * 32 + mt * 16 + (lane >> 2);
#pragma unroll
        for (int nt = 0; nt < 4; nt++) {
            int c = n0 + wn * 32 + nt * 8 + 2 * (lane & 3);
            if (c < 300) {
                Cm[(size_t)r * 300 + c] = acc[mt][nt][0];
                if (c + 1 < 300) Cm[(size_t)r * 300 + c + 1] = acc[mt][nt][1];
                Cm[(size_t)(r + 8) * 300 + c] = acc[mt][nt][2];
                if (c + 1 < 300) Cm[(size_t)(r + 8) * 300 + c + 1] = acc[mt][nt][3];
            }
        }
    }
}

// ---------------- K4: gate (inline) + shift-add combine -> ut fp32 + bf16 hi/lo, norms ----
__global__ void k_comb(const float* __restrict__ udb, const float* __restrict__ idb,
                       const float* __restrict__ wcb) {
    int side = blockIdx.y;
    int bl = blockIdx.x;
    int l = bl % Lsz;
    const float* bias = side ? idb : udb;
    const float* Cm = g_C[side];
    const float* dots = g_dots[side];
    int f = threadIdx.x;

    __shared__ float gsh[3];
    if (f < 3) {
        int j = bl + f - 1;          // neighbor position
        int lj = l + f - 1;
        float gv = 0.f;
        if (lj >= 0 && lj < Lsz) {
            float g = dots[j * 3 + 1] + wcb[0];
            if (lj >= 1)        g += dots[(j - 1) * 3 + 0];
            if (lj <= Lsz - 2)  g += dots[(j + 1) * 3 + 2];
            gv = 1.f / (1.f + __expf(-g));
        }
        gsh[f] = gv;
    }
    __syncthreads();

    float val = 0.f;
    if (f < Fsz) {
        val = bias[f] + gsh[1] * Cm[bl * 300 + Fsz + f];
        if (l >= 1)       val += gsh[0] * Cm[(bl - 1) * 300 + f];
        if (l < Lsz - 1)  val += gsh[2] * Cm[(bl + 1) * 300 + 2 * Fsz + f];
        g_ut[side][bl * Fsz + f] = val;
    }
    if (f < KA) {
        __nv_bfloat16 h = __float2bfloat16(val);
        float lo = val - __bfloat162float(h);
        g_uth[side][(size_t)bl * KA + f] = h;
        g_utl[side][(size_t)bl * KA + f] = __float2bfloat16(lo);
    }
    float sq = val * val;
    sq = warpSum(sq);
    __shared__ float sh[4];
    int lane = threadIdx.x & 31, w = threadIdx.x >> 5;
    if (lane == 0) sh[w] = sq;
    __syncthreads();
    if (threadIdx.x == 0) {
        g_nrm[side][bl] = sh[0] + sh[1] + sh[2] + sh[3];
        g_att[side][bl] = 0.f;
    }
}

// ---------------- K5: tensor-core pairwise attention (bf16 3-pass, phased) ----------------
__global__ __launch_bounds__(256, 3) void k_att_tc() {
    extern __shared__ __align__(16) unsigned char sm[];
    __shared__ float rsum[64], csum[64];
    const int b = blockIdx.z;
    const int l0 = blockIdx.x * 64, m0 = blockIdx.y * 64;
    const int tid = threadIdx.x;
    const int lane = tid & 31, wid = tid >> 5;
    const int wm2 = wid >> 2, wn2 = wid & 3;
    const unsigned sbase = s2u(&sm[0]);

    if (tid < 64) { rsum[tid] = 0.f; csum[tid] = 0.f; }

    for (int i = tid; i < 4 * 64 * 14; i += 256) {
        int arr = i / 896;
        int rem = i - arr * 896;
        int r = rem / 14, c = rem - r * 14;
        int vside = arr >> 1;
        int split = arr & 1;
        int row = (vside ? m0 : l0) + r;
        bool valid = row < Lsz;
        int srow = valid ? row : 0;
        const __nv_bfloat16* src = (split ? g_utl[vside] : g_uth[vside]) +
                                   ((size_t)(b * Lsz + srow)) * KA + c * 8;
        cp16z(sbase + arr * 15360 + r * 240 + c * 16, src, valid);
    }
    cp_commit();
    cp_wait<0>();
    __syncthreads();

    const int l4 = lane & 7, g4 = lane >> 3;
    unsigned aoff[2];
#pragma unroll
    for (int mt = 0; mt < 2; mt++) {
        int rowm = wm2 * 32 + mt * 16 + (g4 & 1) * 8 + l4;
        int koff = (g4 >> 1) * 8;
        aoff[mt] = sbase + (rowm * 120 + koff) * 2;
    }
    unsigned boffv;
    {
        int rown = wn2 * 16 + (g4 >> 1) * 8 + l4;
        int koff = (g4 & 1) * 8;
        boffv = sbase + 30720u + (rown * 120 + koff) * 2;
    }

    float acc[2][2][4];
#pragma unroll
    for (int i = 0; i < 2; i++)
#pragma unroll
        for (int j = 0; j < 2; j++)
#pragma unroll
            for (int q = 0; q < 4; q++) acc[i][j][q] = 0.f;

#pragma unroll
    for (int ck = 0; ck < 7; ck++) {
        const unsigned kb = ck * 32;
        unsigned a_h[2][4], b_h[4];
#pragma unroll
        for (int mt = 0; mt < 2; mt++)
            ldsm4(a_h[mt][0], a_h[mt][1], a_h[mt][2], a_h[mt][3], aoff[mt] + kb);
        ldsm4(b_h[0], b_h[1], b_h[2], b_h[3], boffv + kb);
#pragma unroll
        for (int mt = 0; mt < 2; mt++)
#pragma unroll
            for (int nt = 0; nt < 2; nt++)
                mma_bf16(acc[mt][nt], a_h[mt], &b_h[nt * 2]);
        {
            unsigned b_l[4];
            ldsm4(b_l[0], b_l[1], b_l[2], b_l[3], boffv + kb + 15360);
#pragma unroll
            for (int mt = 0; mt < 2; mt++)
#pragma unroll
                for (int nt = 0; nt < 2; nt++)
                    mma_bf16(acc[mt][nt], a_h[mt], &b_l[nt * 2]);
        }
        {
            unsigned a_l[2][4];
#pragma unroll
            for (int mt = 0; mt < 2; mt++)
                ldsm4(a_l[mt][0], a_l[mt][1], a_l[mt][2], a_l[mt][3], aoff[mt] + kb + 15360);
#pragma unroll
            for (int mt = 0; mt < 2; mt++)
#pragma unroll
                for (int nt = 0; nt < 2; nt++)
                    mma_bf16(acc[mt][nt], a_l[mt], &b_h[nt * 2]);
        }
    }

    float nu[2][2], nv[2][2];
#pragma unroll
    for (int mt = 0; mt < 2; mt++)
#pragma unroll
        for (int h = 0; h < 2; h++) {
            int l = l0 + wm2 * 32 + mt * 16 + h * 8 + (lane >> 2);
            nu[mt][h] = (l < Lsz) ? g_nrm[0][b * Lsz + l] : 0.f;
        }
#pragma unroll
    for (int nt = 0; nt < 2; nt++)
#pragma unroll
        for (int cc = 0; cc < 2; cc++) {
            int m = m0 + wn2 * 16 + nt * 8 + 2 * (lane & 3) + cc;
            nv[nt][cc] = (m < Lsz) ? g_nrm[1][b * Lsz + m] : 0.f;
        }

    float rsv[4] = {0, 0, 0, 0}, csv[4] = {0, 0, 0, 0};
#pragma unroll
    for (int mt = 0; mt < 2; mt++)
#pragma unroll
        for (int nt = 0; nt < 2; nt++)
#pragma unroll
            for (int q = 0; q < 4; q++) {
                int h = q >> 1, cc = q & 1;
                int l = l0 + wm2 * 32 + mt * 16 + h * 8 + (lane >> 2);
                int m = m0 + wn2 * 16 + nt * 8 + 2 * (lane & 3) + cc;
                if (l < Lsz && m < Lsz) {
                    float sq = nu[mt][h] + nv[nt][cc] - 2.f * acc[mt][nt][q];
                    float a = 1.f / (1.f + sqrtf(fmaxf(sq, 1e-12f)));
                    rsv[mt * 2 + h] += a;
                    csv[nt * 2 + cc] += a;
                }
            }
#pragma unroll
    for (int q = 0; q < 4; q++) {
        atomicAdd(&rsum[wm2 * 32 + (q >> 1) * 16 + (q & 1) * 8 + (lane >> 2)], rsv[q]);
        atomicAdd(&csum[wn2 * 16 + (q >> 1) * 8 + 2 * (lane & 3) + (q & 1)], csv[q]);
    }
    __syncthreads();
    if (tid < 64) {
        if (l0 + tid < Lsz) atomicAdd(&g_att[0][b * Lsz + l0 + tid], rsum[tid]);
        if (m0 + tid < Lsz) atomicAdd(&g_att[1][b * Lsz + m0 + tid], csum[tid]);
    }
}

// ---------------- K6: pooling + FC head + id-emb gather ----------------
__global__ void k_head(const float* __restrict__ uacw, const float* __restrict__ uacb,
                       const float* __restrict__ iacw, const float* __restrict__ iacb,
                       const float* __restrict__ ufw,  const float* __restrict__ ufb,
                       const float* __restrict__ ifw,  const float* __restrict__ ifb,
                       const int* __restrict__ uids,   const int* __restrict__ iids,
                       const float* __restrict__ uide, const float* __restrict__ iide,
                       float* __restrict__ out) {
    int b = blockIdx.x;
    int side = blockIdx.y;
    const float* ut  = g_ut[side] + (size_t)b * Lsz * Fsz;
    const float* att = g_att[side] + b * Lsz;
    const float* acw = side ? iacw : uacw;
    const float* acb = side ? iacb : uacb;
    const float* fw  = side ? ifw : ufw;
    const float* fb  = side ? ifb : ufb;
    __shared__ float S[3][Fsz];
    __shared__ float am[Fsz];
    int t = threadIdx.x;

    if (t < Fsz) {
        float s0 = 0.f, s1 = 0.f, s2 = 0.f;
        float pm = 0.f;
        float pc = ut[t] * att[0];
        for (int l = 0; l < Lsz; l++) {
            float pn = (l + 1 < Lsz) ? ut[(l + 1) * Fsz + t] * att[l + 1] : 0.f;
            float s = pm + pc + pn;
            if (l <= Lsz - 3)           s0 += s;
            if (l >= 1 && l <= Lsz - 2) s1 += s;
            if (l >= 2)                 s2 += s;
            pm = pc; pc = pn;
        }
        S[0][t] = s0; S[1][t] = s1; S[2][t] = s2;
    }
    __syncthreads();
    if (t < Fsz) {
        float a = 0.f;
#pragma unroll
        for (int k = 0; k < 3; k++)
            for (int g = 0; g < Fsz; g++)
                a += S[k][g] * acw[(t * 3 + k) * Fsz + g];
        am[t] = acb[t] + a * (1.f / (float)(Lsz - 2));
    }
    __syncthreads();
    if (t < IDs) {
        float o = fb[t];
        for (int f = 0; f < Fsz; f++) o += am[f] * fw[t * Fsz + f];
        o = fmaxf(o, 0.f);
        int base = side ? (Bsz * 2 * IDs) : 0;
        out[base + (b * 2 + 0) * IDs + t] = o;
    }
    if (t >= 64 && t < 64 + IDs) {
        int i = t - 64;
        if (side == 0) {
            out[(b * 2 + 1) * IDs + i] = iide[(size_t)iids[b] * IDs + i];
        } else {
            out[Bsz * 2 * IDs + (b * 2 + 1) * IDs + i] = uide[(size_t)uids[b] * IDs + i];
        }
    }
}

// ---------------- launch ----------------
extern "C" void kernel_launch(void* const* d_in, const int* in_sizes, int n_in,
                              void* d_out, int out_size) {
    const int*   uids = (const int*)d_in[0];
    const int*   iids = (const int*)d_in[1];
    const int*   udoc = (const int*)d_in[2];
    const int*   idoc = (const int*)d_in[3];
    const float* uemb = (const float*)d_in[4];
    const float* iemb = (const float*)d_in[5];
    const float* wcw  = (const float*)d_in[6];
    const float* wcb  = (const float*)d_in[7];
    const float* udcw = (const float*)d_in[8];
    const float* udcb = (const float*)d_in[9];
    const float* idcw = (const float*)d_in[10];
    const float* idcb = (const float*)d_in[11];
    const float* uacw = (const float*)d_in[12];
    const float* uacb = (const float*)d_in[13];
    const float* iacw = (const float*)d_in[14];
    const float* iacb = (const float*)d_in[15];
    const float* ufw  = (const float*)d_in[16];
    const float* ufb  = (const float*)d_in[17];
    const float* ifw  = (const float*)d_in[18];
    const float* ifb  = (const float*)d_in[19];
    const float* uide = (const float*)d_in[20];
    const float* iide = (const float*)d_in[21];
    float* out = (float*)d_out;

    cudaFuncSetAttribute(k_gemm_bf16, cudaFuncAttributeMaxDynamicSharedMemorySize, 4 * 18432);
    cudaFuncSetAttribute(k_att_tc,    cudaFuncAttributeMaxDynamicSharedMemorySize, 4 * 15360);

    k_prep<<<(2 * KP * KP + 255) / 256, 256>>>(udcw, idcw);
    dim3 gBL(BL, 2);
    k_gather<<<gBL, 128>>>(udoc, idoc, uemb, iemb, wcw);
    k_gemm_bf16<<<dim3(5, 250, 2), 256, 4 * 18432>>>();
    k_comb<<<gBL, 128>>>(udcb, idcb, wcb);
    k_att_tc<<<dim3(8, 8, Bsz), 256, 4 * 15360>>>();
    k_head<<<dim3(Bsz, 2), 128>>>(uacw, uacb, iacw, iacb, ufw, ufb, ifw, ifb,
                                  uids, iids, uide, iide, out);
}

// round 10
// speedup vs baseline: 1.0646x; 1.0646x over previous
#include <cuda_runtime.h>
#include <cuda_bf16.h>

#define Bsz 64
#define Lsz 500
#define Dsz 300
#define Fsz 100
#define IDs 32
#define BL  (Bsz*Lsz)   // 32000
#define KP  320         // padded K (and padded N) for the doc GEMM
#define NK  20          // KP / 16 k-iterations
#define KA  112         // padded F for the attention GEMM (7 x 16)

// ---------------- scratch (static device globals; no allocation) ----------------
__device__ __align__(16) __nv_bfloat16 g_Ah[2][BL*KP];    // A hi split (gathered emb, ungated)
__device__ __align__(16) __nv_bfloat16 g_Al[2][BL*KP];    // A lo split
__device__ __align__(16) __nv_bfloat16 g_Wh[2][KP*KP];    // B hi split, layout [n][k]
__device__ __align__(16) __nv_bfloat16 g_Wl[2][KP*KP];    // B lo split
__device__ float g_dots[2][BL*3];
__device__ float g_gatev[2][BL];
__device__ float g_C[2][BL*300];
__device__ float g_ut[2][BL*Fsz];
__device__ __align__(16) __nv_bfloat16 g_uth[2][BL*KA];
__device__ __align__(16) __nv_bfloat16 g_utl[2][BL*KA];
__device__ float g_nrm[2][BL];
__device__ float g_att[2][BL];

__device__ __forceinline__ float warpSum(float v) {
#pragma unroll
    for (int o = 16; o; o >>= 1) v += __shfl_down_sync(0xffffffffu, v, o);
    return v;
}

__device__ __forceinline__ unsigned pack_bf(float x0, float x1, float& r0, float& r1) {
    __nv_bfloat16 h0 = __float2bfloat16(x0);
    __nv_bfloat16 h1 = __float2bfloat16(x1);
    r0 = x0 - __bfloat162float(h0);
    r1 = x1 - __bfloat162float(h1);
    return (unsigned)__bfloat16_as_ushort(h0) | ((unsigned)__bfloat16_as_ushort(h1) << 16);
}

__device__ __forceinline__ void ldsm4(unsigned& r0, unsigned& r1,
                                      unsigned& r2, unsigned& r3, unsigned addr) {
    asm volatile("ldmatrix.sync.aligned.m8n8.x4.shared.b16 {%0,%1,%2,%3}, [%4];"
                 : "=r"(r0), "=r"(r1), "=r"(r2), "=r"(r3) : "r"(addr));
}

__device__ __forceinline__ void mma_bf16(float* c, const unsigned* a, const unsigned* b) {
    asm volatile(
        "mma.sync.aligned.m16n8k16.row.col.f32.bf16.bf16.f32 "
        "{%0,%1,%2,%3}, {%4,%5,%6,%7}, {%8,%9}, {%0,%1,%2,%3};\n"
        : "+f"(c[0]), "+f"(c[1]), "+f"(c[2]), "+f"(c[3])
        : "r"(a[0]), "r"(a[1]), "r"(a[2]), "r"(a[3]), "r"(b[0]), "r"(b[1]));
}

__device__ __forceinline__ void cp16(unsigned sdst, const void* gsrc) {
    asm volatile("cp.async.cg.shared.global [%0], [%1], 16;" :: "r"(sdst), "l"(gsrc));
}
__device__ __forceinline__ void cp16z(unsigned sdst, const void* gsrc, bool v) {
    int sz = v ? 16 : 0;
    asm volatile("cp.async.cg.shared.global [%0], [%1], 16, %2;" :: "r"(sdst), "l"(gsrc), "r"(sz));
}
__device__ __forceinline__ void cp_commit() { asm volatile("cp.async.commit_group;"); }
template <int N>
__device__ __forceinline__ void cp_wait() { asm volatile("cp.async.wait_group %0;" :: "n"(N)); }

__device__ __forceinline__ unsigned s2u(const void* p) {
    unsigned a;
    asm("{ .reg .u64 t; cvta.to.shared.u64 t, %1; cvt.u32.u64 %0, t; }" : "=r"(a) : "l"(p));
    return a;
}

// ---------------- K0: repack + bf16-split doc-conv weights -> [n][k] padded ----------------
__global__ void k_prep(const float* __restrict__ uw, const float* __restrict__ iw) {
    int idx = blockIdx.x * 256 + threadIdx.x;
    if (idx >= 2 * KP * KP) return;
    int side = idx / (KP * KP);
    int r = idx - side * KP * KP;
    int n = r / KP, k = r % KP;
    float x = 0.f;
    if (n < 300 && k < 300) {
        int f = n % Fsz, ks = n / Fsz;
        const float* w = side ? iw : uw;
        x = w[(f * 3 + ks) * Dsz + k];
    }
    __nv_bfloat16 h = __float2bfloat16(x);
    float lo = x - __bfloat162float(h);
    g_Wh[side][n * KP + k] = h;
    g_Wl[side][n * KP + k] = __float2bfloat16(lo);
}

// ---------------- K1: gather + word-gate dots + bf16 hi/lo split (ungated) ----------------
__global__ void k_gather(const int* __restrict__ udoc, const int* __restrict__ idoc,
                         const float* __restrict__ uemb, const float* __restrict__ iemb,
                         const float* __restrict__ wc) {
    int side = blockIdx.y;
    int bl = blockIdx.x;
    const int* doc = side ? idoc : udoc;
    const float* emb = side ? iemb : uemb;
    int row = doc[bl];
    const float* e = emb + (size_t)row * Dsz;
    unsigned* ah = reinterpret_cast<unsigned*>(&g_Ah[side][(size_t)bl * KP]);
    unsigned* al = reinterpret_cast<unsigned*>(&g_Al[side][(size_t)bl * KP]);
    float p0 = 0.f, p1 = 0.f, p2 = 0.f;
    for (int p = threadIdx.x; p < KP / 2; p += 128) {
        int d = 2 * p;
        float x0 = 0.f, x1 = 0.f;
        if (d < 300) {
            float2 v = *reinterpret_cast<const float2*>(&e[d]);
            x0 = v.x; x1 = v.y;
            p0 += x0 * wc[d]       + x1 * wc[d + 1];
            p1 += x0 * wc[300 + d] + x1 * wc[301 + d];
            p2 += x0 * wc[600 + d] + x1 * wc[601 + d];
        }
        float l0, l1;
        unsigned hp = pack_bf(x0, x1, l0, l1);
        __nv_bfloat16 lb0 = __float2bfloat16(l0);
        __nv_bfloat16 lb1 = __float2bfloat16(l1);
        ah[p] = hp;
        al[p] = (unsigned)__bfloat16_as_ushort(lb0) | ((unsigned)__bfloat16_as_ushort(lb1) << 16);
    }
    __shared__ float sh[3][4];
    p0 = warpSum(p0); p1 = warpSum(p1); p2 = warpSum(p2);
    int lane = threadIdx.x & 31, w = threadIdx.x >> 5;
    if (lane == 0) { sh[0][w] = p0; sh[1][w] = p1; sh[2][w] = p2; }
    __syncthreads();
    if (threadIdx.x == 0) {
        g_dots[side][bl * 3 + 0] = sh[0][0] + sh[0][1] + sh[0][2] + sh[0][3];
        g_dots[side][bl * 3 + 1] = sh[1][0] + sh[1][1] + sh[1][2] + sh[1][3];
        g_dots[side][bl * 3 + 2] = sh[2][0] + sh[2][1] + sh[2][2] + sh[2][3];
    }
}

// ---------------- K2: gate scalar + zero att ----------------
__global__ void k_gatev(const float* __restrict__ wcb) {
    int idx = blockIdx.x * 256 + threadIdx.x;
    if (idx >= 2 * BL) return;
    int side = idx / BL;
    int bl = idx - side * BL;
    int l = bl % Lsz;
    float g = g_dots[side][bl * 3 + 1] + wcb[0];
    if (l >= 1)       g += g_dots[side][(bl - 1) * 3 + 0];
    if (l <= Lsz - 2) g += g_dots[side][(bl + 1) * 3 + 2];
    g_gatev[side][bl] = 1.f / (1.f + __expf(-g));
    g_att[side][bl] = 0.f;
}

// ---------------- K3: bf16 mma GEMM (32000x320)@(320x320), 3-term split ----------------
// R7 config (best known): BM=128, BN=64, BK=16, 4-stage, one sync/iter, 2 CTAs/SM.
__global__ __launch_bounds__(256, 2) void k_gemm_bf16() {
    const int side = blockIdx.z;
    float* __restrict__ Cm = g_C[side];

    extern __shared__ __align__(16) unsigned char smbuf[];   // 4 x 18432

    const int tid = threadIdx.x;
    const int lane = tid & 31, wid = tid >> 5;
    const int wm = wid >> 1, wn = wid & 1;
    const int n0 = blockIdx.x * 64;
    const int m0 = blockIdx.y * 128;

    const unsigned smem0 = s2u(&smbuf[0]);

    const int arow = tid >> 1, ahalf = tid & 1;
    const char* gA_h = (const char*)&g_Ah[side][((size_t)(m0 + arow)) * KP + ahalf * 8];
    const char* gA_l = (const char*)&g_Al[side][((size_t)(m0 + arow)) * KP + ahalf * 8];
    const unsigned sA_h = smem0 + arow * 48 + ahalf * 16;
    const unsigned sA_l = sA_h + 6144;
    const int brow = (tid & 127) >> 1;
    const __nv_bfloat16* gBarr = (tid < 128) ? g_Wh[side] : g_Wl[side];
    const char* gB = (const char*)&gBarr[((size_t)(n0 + brow)) * KP + ahalf * 8];
    const unsigned sB = smem0 + ((tid < 128) ? 12288u : 15360u) + brow * 48 + ahalf * 16;

    float acc[2][4][4];
#pragma unroll
    for (int i = 0; i < 2; i++)
#pragma unroll
        for (int j = 0; j < 4; j++)
#pragma unroll
            for (int q = 0; q < 4; q++) acc[i][j][q] = 0.f;

#pragma unroll
    for (int s = 0; s < 3; s++) {
        cp16(sA_h + s * 18432u, gA_h + s * 32);
        cp16(sA_l + s * 18432u, gA_l + s * 32);
        cp16(sB   + s * 18432u, gB   + s * 32);
        cp_commit();
    }

    const int l4 = lane & 7, g4 = lane >> 3;
    unsigned aoff[2];
#pragma unroll
    for (int mt = 0; mt < 2; mt++) {
        int rowm = wm * 32 + mt * 16 + (g4 & 1) * 8 + l4;
        int koff = (g4 >> 1) * 8;
        aoff[mt] = smem0 + (rowm * 24 + koff) * 2;
    }
    unsigned boff[2];
#pragma unroll
    for (int ntp = 0; ntp < 2; ntp++) {
        int rown = wn * 32 + ntp * 16 + (g4 >> 1) * 8 + l4;
        int koff = (g4 & 1) * 8;
        boff[ntp] = smem0 + 12288 + (rown * 24 + koff) * 2;
    }

    for (int it = 0; it < NK; it++) {
        const unsigned sbase = (unsigned)(it & 3) * 18432u;
        if (it < NK - 3) cp_wait<2>(); else cp_wait<0>();
        __syncthreads();

        if (it + 3 < NK) {
            const unsigned nb = (unsigned)((it + 3) & 3) * 18432u;
            cp16(sA_h + nb, gA_h + (it + 3) * 32);
            cp16(sA_l + nb, gA_l + (it + 3) * 32);
            cp16(sB   + nb, gB   + (it + 3) * 32);
            cp_commit();
        }

        unsigned a_h[2][4], a_l[2][4], b_h[2][4], b_l[2][4];
#pragma unroll
        for (int mt = 0; mt < 2; mt++) {
            ldsm4(a_h[mt][0], a_h[mt][1], a_h[mt][2], a_h[mt][3], aoff[mt] + sbase);
            ldsm4(a_l[mt][0], a_l[mt][1], a_l[mt][2], a_l[mt][3], aoff[mt] + sbase + 6144);
        }
#pragma unroll
        for (int ntp = 0; ntp < 2; ntp++) {
            ldsm4(b_h[ntp][0], b_h[ntp][1], b_h[ntp][2], b_h[ntp][3], boff[ntp] + sbase);
            ldsm4(b_l[ntp][0], b_l[ntp][1], b_l[ntp][2], b_l[ntp][3], boff[ntp] + sbase + 3072);
        }
#pragma unroll
        for (int mt = 0; mt < 2; mt++)
#pragma unroll
            for (int nt = 0; nt < 4; nt++) {
                const int bi = nt >> 1, bo = (nt & 1) * 2;
                mma_bf16(acc[mt][nt], a_h[mt], &b_h[bi][bo]);
                mma_bf16(acc[mt][nt], a_h[mt], &b_l[bi][bo]);
                mma_bf16(acc[mt][nt], a_l[mt], &b_h[bi][bo]);
            }
    }

#pragma unroll
    for (int mt = 0; mt < 2; mt++) {
        int r = m0 + wm * 32 + mt * 16 + (lane >> 2);
#pragma unroll
        for (int nt = 0; nt < 4; nt++) {
            int c = n0 + wn * 32 + nt * 8 + 2 * (lane & 3);
            if (c < 300) {
                Cm[(size_t)r * 300 + c] = acc[mt][nt][0];
                if (c + 1 < 300) Cm[(size_t)r * 300 + c + 1] = acc[mt][nt][1];
                Cm[(size_t)(r + 8) * 300 + c] = acc[mt][nt][2];
                if (c + 1 < 300) Cm[(size_t)(r + 8) * 300 + c + 1] = acc[mt][nt][3];
            }
        }
    }
}

// ---------------- K4: warp-per-position combine -> ut fp32 + bf16 hi/lo, norms --------
// grid (2 l-chunks, B, 2 sides), 512 threads = 16 warps; each warp owns l's (stride 16),
// lanes cover f coalesced; norm via warpSum; no per-iter block sync.
__global__ __launch_bounds__(512) void k_comb(const float* __restrict__ udb,
                                              const float* __restrict__ idb) {
    const int side = blockIdx.z;
    const int b = blockIdx.y;
    const int lbase = blockIdx.x * 250;
    const float* bias = side ? idb : udb;
    const float* Cb = g_C[side] + (size_t)b * Lsz * 300;
    const float* gv = g_gatev[side] + b * Lsz;
    float* ut = g_ut[side] + (size_t)b * Lsz * Fsz;
    __nv_bfloat16* uth = g_uth[side] + (size_t)b * Lsz * KA;
    __nv_bfloat16* utl = g_utl[side] + (size_t)b * Lsz * KA;

    __shared__ float sgv[Lsz];
    for (int i = threadIdx.x; i < Lsz; i += 512) sgv[i] = gv[i];
    __syncthreads();

    const int warp = threadIdx.x >> 5, lane = threadIdx.x & 31;
    for (int lo = warp; lo < 250; lo += 16) {
        const int l = lbase + lo;
        const float gc = sgv[l];
        const float gm = (l >= 1)       ? sgv[l - 1] : 0.f;
        const float gp = (l < Lsz - 1)  ? sgv[l + 1] : 0.f;
        const float* c0 = Cb + (size_t)l * 300;
        float nr = 0.f;
#pragma unroll
        for (int itf = 0; itf < 4; itf++) {
            const int f = lane + itf * 32;
            float val = 0.f;
            if (f < Fsz) {
                val = bias[f] + gc * c0[Fsz + f];
                if (l >= 1)       val += gm * c0[f - 300];
                if (l < Lsz - 1)  val += gp * c0[300 + 2 * Fsz + f];
                ut[(size_t)l * Fsz + f] = val;
            }
            if (f < KA) {
                __nv_bfloat16 h = __float2bfloat16(val);
                float lo2 = val - __bfloat162float(h);
                uth[(size_t)l * KA + f] = h;
                utl[(size_t)l * KA + f] = __float2bfloat16(lo2);
            }
            nr += val * val;
        }
        nr = warpSum(nr);
        if (lane == 0) g_nrm[side][b * Lsz + l] = nr;
    }
}

// ---------------- K5: tensor-core pairwise attention (bf16 3-pass) ----------------
__global__ __launch_bounds__(256, 2) void k_att_tc() {
    extern __shared__ __align__(16) unsigned char sm[];
    __shared__ float rsum[64], csum[64];
    const int b = blockIdx.z;
    const int l0 = blockIdx.x * 64, m0 = blockIdx.y * 64;
    const int tid = threadIdx.x;
    const int lane = tid & 31, wid = tid >> 5;
    const int wm2 = wid >> 2, wn2 = wid & 3;
    const unsigned sbase = s2u(&sm[0]);

    if (tid < 64) { rsum[tid] = 0.f; csum[tid] = 0.f; }

    for (int i = tid; i < 4 * 64 * 14; i += 256) {
        int arr = i / 896;
        int rem = i - arr * 896;
        int r = rem / 14, c = rem - r * 14;
        int vside = arr >> 1;
        int split = arr & 1;
        int row = (vside ? m0 : l0) + r;
        bool valid = row < Lsz;
        int srow = valid ? row : 0;
        const __nv_bfloat16* src = (split ? g_utl[vside] : g_uth[vside]) +
                                   ((size_t)(b * Lsz + srow)) * KA + c * 8;
        cp16z(sbase + arr * 15360 + r * 240 + c * 16, src, valid);
    }
    cp_commit();
    cp_wait<0>();
    __syncthreads();

    const int l4 = lane & 7, g4 = lane >> 3;
    unsigned aoff[2];
#pragma unroll
    for (int mt = 0; mt < 2; mt++) {
        int rowm = wm2 * 32 + mt * 16 + (g4 & 1) * 8 + l4;
        int koff = (g4 >> 1) * 8;
        aoff[mt] = sbase + (rowm * 120 + koff) * 2;
    }
    unsigned boffv;
    {
        int rown = wn2 * 16 + (g4 >> 1) * 8 + l4;
        int koff = (g4 & 1) * 8;
        boffv = sbase + 30720u + (rown * 120 + koff) * 2;
    }

    float acc[2][2][4];
#pragma unroll
    for (int i = 0; i < 2; i++)
#pragma unroll
        for (int j = 0; j < 2; j++)
#pragma unroll
            for (int q = 0; q < 4; q++) acc[i][j][q] = 0.f;

#pragma unroll
    for (int ck = 0; ck < 7; ck++) {
        const unsigned kb = ck * 32;
        unsigned a_h[2][4], a_l[2][4], b_h[4], b_l[4];
#pragma unroll
        for (int mt = 0; mt < 2; mt++) {
            ldsm4(a_h[mt][0], a_h[mt][1], a_h[mt][2], a_h[mt][3], aoff[mt] + kb);
            ldsm4(a_l[mt][0], a_l[mt][1], a_l[mt][2], a_l[mt][3], aoff[mt] + kb + 15360);
        }
        ldsm4(b_h[0], b_h[1], b_h[2], b_h[3], boffv + kb);
        ldsm4(b_l[0], b_l[1], b_l[2], b_l[3], boffv + kb + 15360);
#pragma unroll
        for (int mt = 0; mt < 2; mt++)
#pragma unroll
            for (int nt = 0; nt < 2; nt++) {
                mma_bf16(acc[mt][nt], a_h[mt], &b_h[nt * 2]);
                mma_bf16(acc[mt][nt], a_h[mt], &b_l[nt * 2]);
                mma_bf16(acc[mt][nt], a_l[mt], &b_h[nt * 2]);
            }
    }

    float nu[2][2], nv[2][2];
#pragma unroll
    for (int mt = 0; mt < 2; mt++)
#pragma unroll
        for (int h = 0; h < 2; h++) {
            int l = l0 + wm2 * 32 + mt * 16 + h * 8 + (lane >> 2);
            nu[mt][h] = (l < Lsz) ? g_nrm[0][b * Lsz + l] : 0.f;
        }
#pragma unroll
    for (int nt = 0; nt < 2; nt++)
#pragma unroll
        for (int cc = 0; cc < 2; cc++) {
            int m = m0 + wn2 * 16 + nt * 8 + 2 * (lane & 3) + cc;
            nv[nt][cc] = (m < Lsz) ? g_nrm[1][b * Lsz + m] : 0.f;
        }

    float rsv[4] = {0, 0, 0, 0}, csv[4] = {0, 0, 0, 0};
#pragma unroll
    for (int mt = 0; mt < 2; mt++)
#pragma unroll
        for (int nt = 0; nt < 2; nt++)
#pragma unroll
            for (int q = 0; q < 4; q++) {
                int h = q >> 1, cc = q & 1;
                int l = l0 + wm2 * 32 + mt * 16 + h * 8 + (lane >> 2);
                int m = m0 + wn2 * 16 + nt * 8 + 2 * (lane & 3) + cc;
                if (l < Lsz && m < Lsz) {
                    float sq = nu[mt][h] + nv[nt][cc] - 2.f * acc[mt][nt][q];
                    float a = 1.f / (1.f + sqrtf(fmaxf(sq, 1e-12f)));
                    rsv[mt * 2 + h] += a;
                    csv[nt * 2 + cc] += a;
                }
            }
#pragma unroll
    for (int q = 0; q < 4; q++) {
        atomicAdd(&rsum[wm2 * 32 + (q >> 1) * 16 + (q & 1) * 8 + (lane >> 2)], rsv[q]);
        atomicAdd(&csum[wn2 * 16 + (q >> 1) * 8 + 2 * (lane & 3) + (q & 1)], csv[q]);
    }
    __syncthreads();
    if (tid < 64) {
        if (l0 + tid < Lsz) atomicAdd(&g_att[0][b * Lsz + l0 + tid], rsum[tid]);
        if (m0 + tid < Lsz) atomicAdd(&g_att[1][b * Lsz + m0 + tid], csum[tid]);
    }
}

// ---------------- K6: pooling + FC head + id-emb gather ----------------
__global__ void k_head(const float* __restrict__ uacw, const float* __restrict__ uacb,
                       const float* __restrict__ iacw, const float* __restrict__ iacb,
                       const float* __restrict__ ufw,  const float* __restrict__ ufb,
                       const float* __restrict__ ifw,  const float* __restrict__ ifb,
                       const int* __restrict__ uids,   const int* __restrict__ iids,
                       const float* __restrict__ uide, const float* __restrict__ iide,
                       float* __restrict__ out) {
    int b = blockIdx.x;
    int side = blockIdx.y;
    const float* ut  = g_ut[side] + (size_t)b * Lsz * Fsz;
    const float* att = g_att[side] + b * Lsz;
    const float* acw = side ? iacw : uacw;
    const float* acb = side ? iacb : uacb;
    const float* fw  = side ? ifw : ufw;
    const float* fb  = side ? ifb : ufb;
    __shared__ float S[3][Fsz];
    __shared__ float am[Fsz];
    int t = threadIdx.x;

    if (t < Fsz) {
        float s0 = 0.f, s1 = 0.f, s2 = 0.f;
        float pm = 0.f;
        float pc = ut[t] * att[0];
        for (int l = 0; l < Lsz; l++) {
            float pn = (l + 1 < Lsz) ? ut[(l + 1) * Fsz + t] * att[l + 1] : 0.f;
            float s = pm + pc + pn;
            if (l <= Lsz - 3)           s0 += s;
            if (l >= 1 && l <= Lsz - 2) s1 += s;
            if (l >= 2)                 s2 += s;
            pm = pc; pc = pn;
        }
        S[0][t] = s0; S[1][t] = s1; S[2][t] = s2;
    }
    __syncthreads();
    if (t < Fsz) {
        float a = 0.f;
#pragma unroll
        for (int k = 0; k < 3; k++)
            for (int g = 0; g < Fsz; g++)
                a += S[k][g] * acw[(t * 3 + k) * Fsz + g];
        am[t] = acb[t] + a * (1.f / (float)(Lsz - 2));
    }
    __syncthreads();
    if (t < IDs) {
        float o = fb[t];
        for (int f = 0; f < Fsz; f++) o += am[f] * fw[t * Fsz + f];
        o = fmaxf(o, 0.f);
        int base = side ? (Bsz * 2 * IDs) : 0;
        out[base + (b * 2 + 0) * IDs + t] = o;
    }
    if (t >= 64 && t < 64 + IDs) {
        int i = t - 64;
        if (side == 0) {
            out[(b * 2 + 1) * IDs + i] = iide[(size_t)iids[b] * IDs + i];
        } else {
            out[Bsz * 2 * IDs + (b * 2 + 1) * IDs + i] = uide[(size_t)uids[b] * IDs + i];
        }
    }
}

// ---------------- launch ----------------
extern "C" void kernel_launch(void* const* d_in, const int* in_sizes, int n_in,
                              void* d_out, int out_size) {
    const int*   uids = (const int*)d_in[0];
    const int*   iids = (const int*)d_in[1];
    const int*   udoc = (const int*)d_in[2];
    const int*   idoc = (const int*)d_in[3];
    const float* uemb = (const float*)d_in[4];
    const float* iemb = (const float*)d_in[5];
    const float* wcw  = (const float*)d_in[6];
    const float* wcb  = (const float*)d_in[7];
    const float* udcw = (const float*)d_in[8];
    const float* udcb = (const float*)d_in[9];
    const float* idcw = (const float*)d_in[10];
    const float* idcb = (const float*)d_in[11];
    const float* uacw = (const float*)d_in[12];
    const float* uacb = (const float*)d_in[13];
    const float* iacw = (const float*)d_in[14];
    const float* iacb = (const float*)d_in[15];
    const float* ufw  = (const float*)d_in[16];
    const float* ufb  = (const float*)d_in[17];
    const float* ifw  = (const float*)d_in[18];
    const float* ifb  = (const float*)d_in[19];
    const float* uide = (const float*)d_in[20];
    const float* iide = (const float*)d_in[21];
    float* out = (float*)d_out;

    cudaFuncSetAttribute(k_gemm_bf16, cudaFuncAttributeMaxDynamicSharedMemorySize, 4 * 18432);
    cudaFuncSetAttribute(k_att_tc,    cudaFuncAttributeMaxDynamicSharedMemorySize, 4 * 15360);

    k_prep<<<(2 * KP * KP + 255) / 256, 256>>>(udcw, idcw);
    dim3 gBL(BL, 2);
    k_gather<<<gBL, 128>>>(udoc, idoc, uemb, iemb, wcw);
    k_gatev<<<(2 * BL + 255) / 256, 256>>>(wcb);
    k_gemm_bf16<<<dim3(5, 250, 2), 256, 4 * 18432>>>();
    k_comb<<<dim3(2, Bsz, 2), 512>>>(udcb, idcb);
    k_att_tc<<<dim3(8, 8, Bsz), 256, 4 * 15360>>>();
    k_head<<<dim3(Bsz, 2), 128>>>(uacw, uacb, iacw, iacb, ufw, ufb, ifw, ifb,
                                  uids, iids, uide, iide, out);
}

// round 11
// speedup vs baseline: 1.2881x; 1.2100x over previous
#include <cuda_runtime.h>
#include <cuda_bf16.h>
#include <cuda_fp16.h>

#define Bsz 64
#define Lsz 500
#define Dsz 300
#define Fsz 100
#define IDs 32
#define BL  (Bsz*Lsz)   // 32000
#define KP  320         // padded K (and padded N) for the doc GEMM
#define NK  20          // KP / 16 k-iterations
#define KA  112         // padded F for the attention GEMM (7 x 16)
#define STG_G 9216u     // gemm smem stage: A 128x48B + B 64x48B

// ---------------- scratch (static device globals; no allocation) ----------------
__device__ __align__(16) __half g_A[2][BL*KP];    // gathered emb, fp16, ungated
__device__ __align__(16) __half g_W[2][KP*KP];    // doc-conv weights fp16, [n][k]
__device__ float g_dots[2][BL*3];
__device__ float g_gatev[2][BL];
__device__ float g_C[2][BL*300];
__device__ float g_ut[2][BL*Fsz];
__device__ __align__(16) __nv_bfloat16 g_uth[2][BL*KA];
__device__ __align__(16) __nv_bfloat16 g_utl[2][BL*KA];
__device__ float g_nrm[2][BL];
__device__ float g_att[2][BL];

__device__ __forceinline__ float warpSum(float v) {
#pragma unroll
    for (int o = 16; o; o >>= 1) v += __shfl_down_sync(0xffffffffu, v, o);
    return v;
}

__device__ __forceinline__ void ldsm4(unsigned& r0, unsigned& r1,
                                      unsigned& r2, unsigned& r3, unsigned addr) {
    asm volatile("ldmatrix.sync.aligned.m8n8.x4.shared.b16 {%0,%1,%2,%3}, [%4];"
                 : "=r"(r0), "=r"(r1), "=r"(r2), "=r"(r3) : "r"(addr));
}

__device__ __forceinline__ void mma_fp16(float* c, const unsigned* a, const unsigned* b) {
    asm volatile(
        "mma.sync.aligned.m16n8k16.row.col.f32.f16.f16.f32 "
        "{%0,%1,%2,%3}, {%4,%5,%6,%7}, {%8,%9}, {%0,%1,%2,%3};\n"
        : "+f"(c[0]), "+f"(c[1]), "+f"(c[2]), "+f"(c[3])
        : "r"(a[0]), "r"(a[1]), "r"(a[2]), "r"(a[3]), "r"(b[0]), "r"(b[1]));
}

__device__ __forceinline__ void mma_bf16(float* c, const unsigned* a, const unsigned* b) {
    asm volatile(
        "mma.sync.aligned.m16n8k16.row.col.f32.bf16.bf16.f32 "
        "{%0,%1,%2,%3}, {%4,%5,%6,%7}, {%8,%9}, {%0,%1,%2,%3};\n"
        : "+f"(c[0]), "+f"(c[1]), "+f"(c[2]), "+f"(c[3])
        : "r"(a[0]), "r"(a[1]), "r"(a[2]), "r"(a[3]), "r"(b[0]), "r"(b[1]));
}

__device__ __forceinline__ void cp16(unsigned sdst, const void* gsrc) {
    asm volatile("cp.async.cg.shared.global [%0], [%1], 16;" :: "r"(sdst), "l"(gsrc));
}
__device__ __forceinline__ void cp16z(unsigned sdst, const void* gsrc, bool v) {
    int sz = v ? 16 : 0;
    asm volatile("cp.async.cg.shared.global [%0], [%1], 16, %2;" :: "r"(sdst), "l"(gsrc), "r"(sz));
}
__device__ __forceinline__ void cp_commit() { asm volatile("cp.async.commit_group;"); }
template <int N>
__device__ __forceinline__ void cp_wait() { asm volatile("cp.async.wait_group %0;" :: "n"(N)); }

__device__ __forceinline__ unsigned s2u(const void* p) {
    unsigned a;
    asm("{ .reg .u64 t; cvta.to.shared.u64 t, %1; cvt.u32.u64 %0, t; }" : "=r"(a) : "l"(p));
    return a;
}

// ---------------- K0: repack doc-conv weights fp16 -> [n][k] padded ----------------
__global__ void k_prep(const float* __restrict__ uw, const float* __restrict__ iw) {
    int idx = blockIdx.x * 256 + threadIdx.x;
    if (idx >= 2 * KP * KP) return;
    int side = idx / (KP * KP);
    int r = idx - side * KP * KP;
    int n = r / KP, k = r % KP;
    float x = 0.f;
    if (n < 300 && k < 300) {
        int f = n % Fsz, ks = n / Fsz;
        const float* w = side ? iw : uw;
        x = w[(f * 3 + ks) * Dsz + k];
    }
    g_W[side][n * KP + k] = __float2half(x);
}

// ---------------- K1: gather + word-gate dots + fp16 convert (ungated) ----------------
__global__ void k_gather(const int* __restrict__ udoc, const int* __restrict__ idoc,
                         const float* __restrict__ uemb, const float* __restrict__ iemb,
                         const float* __restrict__ wc) {
    int side = blockIdx.y;
    int bl = blockIdx.x;
    const int* doc = side ? idoc : udoc;
    const float* emb = side ? iemb : uemb;
    int row = doc[bl];
    const float* e = emb + (size_t)row * Dsz;
    unsigned* ad = reinterpret_cast<unsigned*>(&g_A[side][(size_t)bl * KP]);
    float p0 = 0.f, p1 = 0.f, p2 = 0.f;
    for (int p = threadIdx.x; p < KP / 2; p += 128) {
        int d = 2 * p;
        float x0 = 0.f, x1 = 0.f;
        if (d < 300) {
            float2 v = *reinterpret_cast<const float2*>(&e[d]);
            x0 = v.x; x1 = v.y;
            p0 += x0 * wc[d]       + x1 * wc[d + 1];
            p1 += x0 * wc[300 + d] + x1 * wc[301 + d];
            p2 += x0 * wc[600 + d] + x1 * wc[601 + d];
        }
        __half h0 = __float2half(x0);
        __half h1 = __float2half(x1);
        ad[p] = (unsigned)__half_as_ushort(h0) | ((unsigned)__half_as_ushort(h1) << 16);
    }
    __shared__ float sh[3][4];
    p0 = warpSum(p0); p1 = warpSum(p1); p2 = warpSum(p2);
    int lane = threadIdx.x & 31, w = threadIdx.x >> 5;
    if (lane == 0) { sh[0][w] = p0; sh[1][w] = p1; sh[2][w] = p2; }
    __syncthreads();
    if (threadIdx.x == 0) {
        g_dots[side][bl * 3 + 0] = sh[0][0] + sh[0][1] + sh[0][2] + sh[0][3];
        g_dots[side][bl * 3 + 1] = sh[1][0] + sh[1][1] + sh[1][2] + sh[1][3];
        g_dots[side][bl * 3 + 2] = sh[2][0] + sh[2][1] + sh[2][2] + sh[2][3];
    }
}

// ---------------- K2: gate scalar + zero att ----------------
__global__ void k_gatev(const float* __restrict__ wcb) {
    int idx = blockIdx.x * 256 + threadIdx.x;
    if (idx >= 2 * BL) return;
    int side = idx / BL;
    int bl = idx - side * BL;
    int l = bl % Lsz;
    float g = g_dots[side][bl * 3 + 1] + wcb[0];
    if (l >= 1)       g += g_dots[side][(bl - 1) * 3 + 0];
    if (l <= Lsz - 2) g += g_dots[side][(bl + 1) * 3 + 2];
    g_gatev[side][bl] = 1.f / (1.f + __expf(-g));
    g_att[side][bl] = 0.f;
}

// ---------------- K3: fp16 single-pass mma GEMM (32000x320)@(320x320) ----------------
// BM=128, BN=64, BK=16, 256 threads (8 warps 4x2), warp tile 32x32.
// stage 9216B: A 128 rows x 48B stride @0, B 64 rows x 48B stride @6144. 4 stages.
__global__ __launch_bounds__(256, 3) void k_gemm_fp16() {
    const int side = blockIdx.z;
    float* __restrict__ Cm = g_C[side];

    extern __shared__ __align__(16) unsigned char smbuf[];   // 4 x 9216

    const int tid = threadIdx.x;
    const int lane = tid & 31, wid = tid >> 5;
    const int wm = wid >> 1, wn = wid & 1;
    const int n0 = blockIdx.x * 64;
    const int m0 = blockIdx.y * 128;

    const unsigned smem0 = s2u(&smbuf[0]);

    // cp.async mapping: every thread 1 A-chunk; threads <128 also 1 B-chunk
    const int arow = tid >> 1, ahalf = tid & 1;
    const char* gA = (const char*)&g_A[side][((size_t)(m0 + arow)) * KP + ahalf * 8];
    const unsigned sA = smem0 + arow * 48 + ahalf * 16;
    const int brow = tid >> 1;           // valid for tid<128: 0..63
    const char* gB = (const char*)&g_W[side][((size_t)(n0 + (brow & 63))) * KP + ahalf * 8];
    const unsigned sB = smem0 + 6144u + (brow & 63) * 48 + ahalf * 16;
    const bool hasB = tid < 128;

    float acc[2][4][4];
#pragma unroll
    for (int i = 0; i < 2; i++)
#pragma unroll
        for (int j = 0; j < 4; j++)
#pragma unroll
            for (int q = 0; q < 4; q++) acc[i][j][q] = 0.f;

#pragma unroll
    for (int s = 0; s < 3; s++) {
        cp16(sA + s * STG_G, gA + s * 32);
        if (hasB) cp16(sB + s * STG_G, gB + s * 32);
        cp_commit();
    }

    const int l4 = lane & 7, g4 = lane >> 3;
    unsigned aoff[2];
#pragma unroll
    for (int mt = 0; mt < 2; mt++) {
        int rowm = wm * 32 + mt * 16 + (g4 & 1) * 8 + l4;
        aoff[mt] = smem0 + rowm * 48 + (g4 >> 1) * 16;
    }
    unsigned boff[2];
#pragma unroll
    for (int ntp = 0; ntp < 2; ntp++) {
        int rown = wn * 32 + ntp * 16 + (g4 >> 1) * 8 + l4;
        boff[ntp] = smem0 + 6144u + rown * 48 + (g4 & 1) * 16;
    }

    for (int it = 0; it < NK; it++) {
        const unsigned sbase = (unsigned)(it & 3) * STG_G;
        if (it < NK - 3) cp_wait<2>(); else cp_wait<0>();
        __syncthreads();

        if (it + 3 < NK) {
            const unsigned nb = (unsigned)((it + 3) & 3) * STG_G;
            cp16(sA + nb, gA + (it + 3) * 32);
            if (hasB) cp16(sB + nb, gB + (it + 3) * 32);
            cp_commit();
        }

        unsigned a[2][4], b[2][4];
#pragma unroll
        for (int mt = 0; mt < 2; mt++)
            ldsm4(a[mt][0], a[mt][1], a[mt][2], a[mt][3], aoff[mt] + sbase);
#pragma unroll
        for (int ntp = 0; ntp < 2; ntp++)
            ldsm4(b[ntp][0], b[ntp][1], b[ntp][2], b[ntp][3], boff[ntp] + sbase);
#pragma unroll
        for (int mt = 0; mt < 2; mt++)
#pragma unroll
            for (int nt = 0; nt < 4; nt++)
                mma_fp16(acc[mt][nt], a[mt], &b[nt >> 1][(nt & 1) * 2]);
    }

    // epilogue
#pragma unroll
    for (int mt = 0; mt < 2; mt++) {
        int r = m0 + wm * 32 + mt * 16 + (lane >> 2);
#pragma unroll
        for (int nt = 0; nt < 4; nt++) {
            int c = n0 + wn * 32 + nt * 8 + 2 * (lane & 3);
            if (c < 300) {
                Cm[(size_t)r * 300 + c] = acc[mt][nt][0];
                if (c + 1 < 300) Cm[(size_t)r * 300 + c + 1] = acc[mt][nt][1];
                Cm[(size_t)(r + 8) * 300 + c] = acc[mt][nt][2];
                if (c + 1 < 300) Cm[(size_t)(r + 8) * 300 + c + 1] = acc[mt][nt][3];
            }
        }
    }
}

// ---------------- K4: warp-per-position combine -> ut fp32 + bf16 hi/lo, norms --------
__global__ __launch_bounds__(512) void k_comb(const float* __restrict__ udb,
                                              const float* __restrict__ idb) {
    const int side = blockIdx.z;
    const int b = blockIdx.y;
    const int lbase = blockIdx.x * 250;
    const float* bias = side ? idb : udb;
    const float* Cb = g_C[side] + (size_t)b * Lsz * 300;
    const float* gv = g_gatev[side] + b * Lsz;
    float* ut = g_ut[side] + (size_t)b * Lsz * Fsz;
    __nv_bfloat16* uth = g_uth[side] + (size_t)b * Lsz * KA;
    __nv_bfloat16* utl = g_utl[side] + (size_t)b * Lsz * KA;

    __shared__ float sgv[Lsz];
    for (int i = threadIdx.x; i < Lsz; i += 512) sgv[i] = gv[i];
    __syncthreads();

    const int warp = threadIdx.x >> 5, lane = threadIdx.x & 31;
    for (int lo = warp; lo < 250; lo += 16) {
        const int l = lbase + lo;
        const float gc = sgv[l];
        const float gm = (l >= 1)       ? sgv[l - 1] : 0.f;
        const float gp = (l < Lsz - 1)  ? sgv[l + 1] : 0.f;
        const float* c0 = Cb + (size_t)l * 300;
        float nr = 0.f;
#pragma unroll
        for (int itf = 0; itf < 4; itf++) {
            const int f = lane + itf * 32;
            float val = 0.f;
            if (f < Fsz) {
                val = bias[f] + gc * c0[Fsz + f];
                if (l >= 1)       val += gm * c0[f - 300];
                if (l < Lsz - 1)  val += gp * c0[300 + 2 * Fsz + f];
                ut[(size_t)l * Fsz + f] = val;
            }
            if (f < KA) {
                __nv_bfloat16 h = __float2bfloat16(val);
                float lo2 = val - __bfloat162float(h);
                uth[(size_t)l * KA + f] = h;
                utl[(size_t)l * KA + f] = __float2bfloat16(lo2);
            }
            nr += val * val;
        }
        nr = warpSum(nr);
        if (lane == 0) g_nrm[side][b * Lsz + l] = nr;
    }
}

// ---------------- K5: tensor-core pairwise attention (bf16 3-pass) ----------------
__global__ __launch_bounds__(256, 2) void k_att_tc() {
    extern __shared__ __align__(16) unsigned char sm[];
    __shared__ float rsum[64], csum[64];
    const int b = blockIdx.z;
    const int l0 = blockIdx.x * 64, m0 = blockIdx.y * 64;
    const int tid = threadIdx.x;
    const int lane = tid & 31, wid = tid >> 5;
    const int wm2 = wid >> 2, wn2 = wid & 3;
    const unsigned sbase = s2u(&sm[0]);

    if (tid < 64) { rsum[tid] = 0.f; csum[tid] = 0.f; }

    for (int i = tid; i < 4 * 64 * 14; i += 256) {
        int arr = i / 896;
        int rem = i - arr * 896;
        int r = rem / 14, c = rem - r * 14;
        int vside = arr >> 1;
        int split = arr & 1;
        int row = (vside ? m0 : l0) + r;
        bool valid = row < Lsz;
        int srow = valid ? row : 0;
        const __nv_bfloat16* src = (split ? g_utl[vside] : g_uth[vside]) +
                                   ((size_t)(b * Lsz + srow)) * KA + c * 8;
        cp16z(sbase + arr * 15360 + r * 240 + c * 16, src, valid);
    }
    cp_commit();
    cp_wait<0>();
    __syncthreads();

    const int l4 = lane & 7, g4 = lane >> 3;
    unsigned aoff[2];
#pragma unroll
    for (int mt = 0; mt < 2; mt++) {
        int rowm = wm2 * 32 + mt * 16 + (g4 & 1) * 8 + l4;
        int koff = (g4 >> 1) * 8;
        aoff[mt] = sbase + (rowm * 120 + koff) * 2;
    }
    unsigned boffv;
    {
        int rown = wn2 * 16 + (g4 >> 1) * 8 + l4;
        int koff = (g4 & 1) * 8;
        boffv = sbase + 30720u + (rown * 120 + koff) * 2;
    }

    float acc[2][2][4];
#pragma unroll
    for (int i = 0; i < 2; i++)
#pragma unroll
        for (int j = 0; j < 2; j++)
#pragma unroll
            for (int q = 0; q < 4; q++) acc[i][j][q] = 0.f;

#pragma unroll
    for (int ck = 0; ck < 7; ck++) {
        const unsigned kb = ck * 32;
        unsigned a_h[2][4], a_l[2][4], b_h[4], b_l[4];
#pragma unroll
        for (int mt = 0; mt < 2; mt++) {
            ldsm4(a_h[mt][0], a_h[mt][1], a_h[mt][2], a_h[mt][3], aoff[mt] + kb);
            ldsm4(a_l[mt][0], a_l[mt][1], a_l[mt][2], a_l[mt][3], aoff[mt] + kb + 15360);
        }
        ldsm4(b_h[0], b_h[1], b_h[2], b_h[3], boffv + kb);
        ldsm4(b_l[0], b_l[1], b_l[2], b_l[3], boffv + kb + 15360);
#pragma unroll
        for (int mt = 0; mt < 2; mt++)
#pragma unroll
            for (int nt = 0; nt < 2; nt++) {
                mma_bf16(acc[mt][nt], a_h[mt], &b_h[nt * 2]);
                mma_bf16(acc[mt][nt], a_h[mt], &b_l[nt * 2]);
                mma_bf16(acc[mt][nt], a_l[mt], &b_h[nt * 2]);
            }
    }

    float nu[2][2], nv[2][2];
#pragma unroll
    for (int mt = 0; mt < 2; mt++)
#pragma unroll
        for (int h = 0; h < 2; h++) {
            int l = l0 + wm2 * 32 + mt * 16 + h * 8 + (lane >> 2);
            nu[mt][h] = (l < Lsz) ? g_nrm[0][b * Lsz + l] : 0.f;
        }
#pragma unroll
    for (int nt = 0; nt < 2; nt++)
#pragma unroll
        for (int cc = 0; cc < 2; cc++) {
            int m = m0 + wn2 * 16 + nt * 8 + 2 * (lane & 3) + cc;
            nv[nt][cc] = (m < Lsz) ? g_nrm[1][b * Lsz + m] : 0.f;
        }

    float rsv[4] = {0, 0, 0, 0}, csv[4] = {0, 0, 0, 0};
#pragma unroll
    for (int mt = 0; mt < 2; mt++)
#pragma unroll
        for (int nt = 0; nt < 2; nt++)
#pragma unroll
            for (int q = 0; q < 4; q++) {
                int h = q >> 1, cc = q & 1;
                int l = l0 + wm2 * 32 + mt * 16 + h * 8 + (lane >> 2);
                int m = m0 + wn2 * 16 + nt * 8 + 2 * (lane & 3) + cc;
                if (l < Lsz && m < Lsz) {
                    float sq = nu[mt][h] + nv[nt][cc] - 2.f * acc[mt][nt][q];
                    float a = 1.f / (1.f + sqrtf(fmaxf(sq, 1e-12f)));
                    rsv[mt * 2 + h] += a;
                    csv[nt * 2 + cc] += a;
                }
            }
#pragma unroll
    for (int q = 0; q < 4; q++) {
        atomicAdd(&rsum[wm2 * 32 + (q >> 1) * 16 + (q & 1) * 8 + (lane >> 2)], rsv[q]);
        atomicAdd(&csum[wn2 * 16 + (q >> 1) * 8 + 2 * (lane & 3) + (q & 1)], csv[q]);
    }
    __syncthreads();
    if (tid < 64) {
        if (l0 + tid < Lsz) atomicAdd(&g_att[0][b * Lsz + l0 + tid], rsum[tid]);
        if (m0 + tid < Lsz) atomicAdd(&g_att[1][b * Lsz + m0 + tid], csum[tid]);
    }
}

// ---------------- K6: pooling + FC head + id-emb gather ----------------
__global__ void k_head(const float* __restrict__ uacw, const float* __restrict__ uacb,
                       const float* __restrict__ iacw, const float* __restrict__ iacb,
                       const float* __restrict__ ufw,  const float* __restrict__ ufb,
                       const float* __restrict__ ifw,  const float* __restrict__ ifb,
                       const int* __restrict__ uids,   const int* __restrict__ iids,
                       const float* __restrict__ uide, const float* __restrict__ iide,
                       float* __restrict__ out) {
    int b = blockIdx.x;
    int side = blockIdx.y;
    const float* ut  = g_ut[side] + (size_t)b * Lsz * Fsz;
    const float* att = g_att[side] + b * Lsz;
    const float* acw = side ? iacw : uacw;
    const float* acb = side ? iacb : uacb;
    const float* fw  = side ? ifw : ufw;
    const float* fb  = side ? ifb : ufb;
    __shared__ float S[3][Fsz];
    __shared__ float am[Fsz];
    int t = threadIdx.x;

    if (t < Fsz) {
        float s0 = 0.f, s1 = 0.f, s2 = 0.f;
        float pm = 0.f;
        float pc = ut[t] * att[0];
        for (int l = 0; l < Lsz; l++) {
            float pn = (l + 1 < Lsz) ? ut[(l + 1) * Fsz + t] * att[l + 1] : 0.f;
            float s = pm + pc + pn;
            if (l <= Lsz - 3)           s0 += s;
            if (l >= 1 && l <= Lsz - 2) s1 += s;
            if (l >= 2)                 s2 += s;
            pm = pc; pc = pn;
        }
        S[0][t] = s0; S[1][t] = s1; S[2][t] = s2;
    }
    __syncthreads();
    if (t < Fsz) {
        float a = 0.f;
#pragma unroll
        for (int k = 0; k < 3; k++)
            for (int g = 0; g < Fsz; g++)
                a += S[k][g] * acw[(t * 3 + k) * Fsz + g];
        am[t] = acb[t] + a * (1.f / (float)(Lsz - 2));
    }
    __syncthreads();
    if (t < IDs) {
        float o = fb[t];
        for (int f = 0; f < Fsz; f++) o += am[f] * fw[t * Fsz + f];
        o = fmaxf(o, 0.f);
        int base = side ? (Bsz * 2 * IDs) : 0;
        out[base + (b * 2 + 0) * IDs + t] = o;
    }
    if (t >= 64 && t < 64 + IDs) {
        int i = t - 64;
        if (side == 0) {
            out[(b * 2 + 1) * IDs + i] = iide[(size_t)iids[b] * IDs + i];
        } else {
            out[Bsz * 2 * IDs + (b * 2 + 1) * IDs + i] = uide[(size_t)uids[b] * IDs + i];
        }
    }
}

// ---------------- launch ----------------
extern "C" void kernel_launch(void* const* d_in, const int* in_sizes, int n_in,
                              void* d_out, int out_size) {
    const int*   uids = (const int*)d_in[0];
    const int*   iids = (const int*)d_in[1];
    const int*   udoc = (const int*)d_in[2];
    const int*   idoc = (const int*)d_in[3];
    const float* uemb = (const float*)d_in[4];
    const float* iemb = (const float*)d_in[5];
    const float* wcw  = (const float*)d_in[6];
    const float* wcb  = (const float*)d_in[7];
    const float* udcw = (const float*)d_in[8];
    const float* udcb = (const float*)d_in[9];
    const float* idcw = (const float*)d_in[10];
    const float* idcb = (const float*)d_in[11];
    const float* uacw = (const float*)d_in[12];
    const float* uacb = (const float*)d_in[13];
    const float* iacw = (const float*)d_in[14];
    const float* iacb = (const float*)d_in[15];
    const float* ufw  = (const float*)d_in[16];
    const float* ufb  = (const float*)d_in[17];
    const float* ifw  = (const float*)d_in[18];
    const float* ifb  = (const float*)d_in[19];
    const float* uide = (const float*)d_in[20];
    const float* iide = (const float*)d_in[21];
    float* out = (float*)d_out;

    cudaFuncSetAttribute(k_gemm_fp16, cudaFuncAttributeMaxDynamicSharedMemorySize, 4 * (int)STG_G);
    cudaFuncSetAttribute(k_att_tc,    cudaFuncAttributeMaxDynamicSharedMemorySize, 4 * 15360);

    k_prep<<<(2 * KP * KP + 255) / 256, 256>>>(udcw, idcw);
    dim3 gBL(BL, 2);
    k_gather<<<gBL, 128>>>(udoc, idoc, uemb, iemb, wcw);
    k_gatev<<<(2 * BL + 255) / 256, 256>>>(wcb);
    k_gemm_fp16<<<dim3(5, 250, 2), 256, 4 * STG_G>>>();
    k_comb<<<dim3(2, Bsz, 2), 512>>>(udcb, idcb);
    k_att_tc<<<dim3(8, 8, Bsz), 256, 4 * 15360>>>();
    k_head<<<dim3(Bsz, 2), 128>>>(uacw, uacb, iacw, iacb, ufw, ufb, ifw, ifb,
                                  uids, iids, uide, iide, out);
}

// round 12
// speedup vs baseline: 1.3251x; 1.0287x over previous
#include <cuda_runtime.h>
#include <cuda_bf16.h>
#include <cuda_fp16.h>

#define Bsz 64
#define Lsz 500
#define Dsz 300
#define Fsz 100
#define IDs 32
#define BL  (Bsz*Lsz)   // 32000
#define KP  320         // padded K (and padded N) for the doc GEMM
#define NK  20          // KP / 16 k-iterations
#define KA  112         // padded F for the attention GEMM (7 x 16)
#define STG_G 9216u     // gemm smem stage: A 128x48B + B 64x48B

// ---------------- scratch (static device globals; no allocation) ----------------
__device__ __align__(16) __half g_A[2][BL*KP];    // gathered emb, fp16, ungated
__device__ __align__(16) __half g_W[2][KP*KP];    // doc-conv weights fp16, [n][k]
__device__ float g_dots[2][BL*3];
__device__ float g_C[2][BL*300];
__device__ float g_ut[2][BL*Fsz];                 // fp32 for k_head
__device__ __align__(16) __half g_utf[2][BL*KA];  // fp16 for k_att
__device__ float g_nrm[2][BL];
__device__ float g_att[2][BL];

__device__ __forceinline__ float warpSum(float v) {
#pragma unroll
    for (int o = 16; o; o >>= 1) v += __shfl_down_sync(0xffffffffu, v, o);
    return v;
}

__device__ __forceinline__ void ldsm4(unsigned& r0, unsigned& r1,
                                      unsigned& r2, unsigned& r3, unsigned addr) {
    asm volatile("ldmatrix.sync.aligned.m8n8.x4.shared.b16 {%0,%1,%2,%3}, [%4];"
                 : "=r"(r0), "=r"(r1), "=r"(r2), "=r"(r3) : "r"(addr));
}

__device__ __forceinline__ void mma_fp16(float* c, const unsigned* a, const unsigned* b) {
    asm volatile(
        "mma.sync.aligned.m16n8k16.row.col.f32.f16.f16.f32 "
        "{%0,%1,%2,%3}, {%4,%5,%6,%7}, {%8,%9}, {%0,%1,%2,%3};\n"
        : "+f"(c[0]), "+f"(c[1]), "+f"(c[2]), "+f"(c[3])
        : "r"(a[0]), "r"(a[1]), "r"(a[2]), "r"(a[3]), "r"(b[0]), "r"(b[1]));
}

__device__ __forceinline__ void cp16(unsigned sdst, const void* gsrc) {
    asm volatile("cp.async.cg.shared.global [%0], [%1], 16;" :: "r"(sdst), "l"(gsrc));
}
__device__ __forceinline__ void cp16z(unsigned sdst, const void* gsrc, bool v) {
    int sz = v ? 16 : 0;
    asm volatile("cp.async.cg.shared.global [%0], [%1], 16, %2;" :: "r"(sdst), "l"(gsrc), "r"(sz));
}
__device__ __forceinline__ void cp_commit() { asm volatile("cp.async.commit_group;"); }
template <int N>
__device__ __forceinline__ void cp_wait() { asm volatile("cp.async.wait_group %0;" :: "n"(N)); }

__device__ __forceinline__ unsigned s2u(const void* p) {
    unsigned a;
    asm("{ .reg .u64 t; cvta.to.shared.u64 t, %1; cvt.u32.u64 %0, t; }" : "=r"(a) : "l"(p));
    return a;
}

// ---------------- K0: repack doc-conv weights fp16 -> [n][k] padded ----------------
__global__ void k_prep(const float* __restrict__ uw, const float* __restrict__ iw) {
    int idx = blockIdx.x * 256 + threadIdx.x;
    if (idx >= 2 * KP * KP) return;
    int side = idx / (KP * KP);
    int r = idx - side * KP * KP;
    int n = r / KP, k = r % KP;
    float x = 0.f;
    if (n < 300 && k < 300) {
        int f = n % Fsz, ks = n / Fsz;
        const float* w = side ? iw : uw;
        x = w[(f * 3 + ks) * Dsz + k];
    }
    g_W[side][n * KP + k] = __float2half(x);
}

// ---------------- K1: gather + word-gate dots + fp16 convert (ungated) ----------------
__global__ void k_gather(const int* __restrict__ udoc, const int* __restrict__ idoc,
                         const float* __restrict__ uemb, const float* __restrict__ iemb,
                         const float* __restrict__ wc) {
    int side = blockIdx.y;
    int bl = blockIdx.x;
    const int* doc = side ? idoc : udoc;
    const float* emb = side ? iemb : uemb;
    int row = doc[bl];
    const float* e = emb + (size_t)row * Dsz;
    unsigned* ad = reinterpret_cast<unsigned*>(&g_A[side][(size_t)bl * KP]);
    float p0 = 0.f, p1 = 0.f, p2 = 0.f;
    for (int p = threadIdx.x; p < KP / 2; p += 128) {
        int d = 2 * p;
        float x0 = 0.f, x1 = 0.f;
        if (d < 300) {
            float2 v = *reinterpret_cast<const float2*>(&e[d]);
            x0 = v.x; x1 = v.y;
            p0 += x0 * wc[d]       + x1 * wc[d + 1];
            p1 += x0 * wc[300 + d] + x1 * wc[301 + d];
            p2 += x0 * wc[600 + d] + x1 * wc[601 + d];
        }
        __half h0 = __float2half(x0);
        __half h1 = __float2half(x1);
        ad[p] = (unsigned)__half_as_ushort(h0) | ((unsigned)__half_as_ushort(h1) << 16);
    }
    __shared__ float sh[3][4];
    p0 = warpSum(p0); p1 = warpSum(p1); p2 = warpSum(p2);
    int lane = threadIdx.x & 31, w = threadIdx.x >> 5;
    if (lane == 0) { sh[0][w] = p0; sh[1][w] = p1; sh[2][w] = p2; }
    __syncthreads();
    if (threadIdx.x == 0) {
        g_dots[side][bl * 3 + 0] = sh[0][0] + sh[0][1] + sh[0][2] + sh[0][3];
        g_dots[side][bl * 3 + 1] = sh[1][0] + sh[1][1] + sh[1][2] + sh[1][3];
        g_dots[side][bl * 3 + 2] = sh[2][0] + sh[2][1] + sh[2][2] + sh[2][3];
    }
}

// ---------------- K3: fp16 single-pass mma GEMM (32000x320)@(320x320) ----------------
__global__ __launch_bounds__(256, 3) void k_gemm_fp16() {
    const int side = blockIdx.z;
    float* __restrict__ Cm = g_C[side];

    extern __shared__ __align__(16) unsigned char smbuf[];   // 4 x 9216

    const int tid = threadIdx.x;
    const int lane = tid & 31, wid = tid >> 5;
    const int wm = wid >> 1, wn = wid & 1;
    const int n0 = blockIdx.x * 64;
    const int m0 = blockIdx.y * 128;

    const unsigned smem0 = s2u(&smbuf[0]);

    const int arow = tid >> 1, ahalf = tid & 1;
    const char* gA = (const char*)&g_A[side][((size_t)(m0 + arow)) * KP + ahalf * 8];
    const unsigned sA = smem0 + arow * 48 + ahalf * 16;
    const int brow = tid >> 1;
    const char* gB = (const char*)&g_W[side][((size_t)(n0 + (brow & 63))) * KP + ahalf * 8];
    const unsigned sB = smem0 + 6144u + (brow & 63) * 48 + ahalf * 16;
    const bool hasB = tid < 128;

    float acc[2][4][4];
#pragma unroll
    for (int i = 0; i < 2; i++)
#pragma unroll
        for (int j = 0; j < 4; j++)
#pragma unroll
            for (int q = 0; q < 4; q++) acc[i][j][q] = 0.f;

#pragma unroll
    for (int s = 0; s < 3; s++) {
        cp16(sA + s * STG_G, gA + s * 32);
        if (hasB) cp16(sB + s * STG_G, gB + s * 32);
        cp_commit();
    }

    const int l4 = lane & 7, g4 = lane >> 3;
    unsigned aoff[2];
#pragma unroll
    for (int mt = 0; mt < 2; mt++) {
        int rowm = wm * 32 + mt * 16 + (g4 & 1) * 8 + l4;
        aoff[mt] = smem0 + rowm * 48 + (g4 >> 1) * 16;
    }
    unsigned boff[2];
#pragma unroll
    for (int ntp = 0; ntp < 2; ntp++) {
        int rown = wn * 32 + ntp * 16 + (g4 >> 1) * 8 + l4;
        boff[ntp] = smem0 + 6144u + rown * 48 + (g4 & 1) * 16;
    }

    for (int it = 0; it < NK; it++) {
        const unsigned sbase = (unsigned)(it & 3) * STG_G;
        if (it < NK - 3) cp_wait<2>(); else cp_wait<0>();
        __syncthreads();

        if (it + 3 < NK) {
            const unsigned nb = (unsigned)((it + 3) & 3) * STG_G;
            cp16(sA + nb, gA + (it + 3) * 32);
            if (hasB) cp16(sB + nb, gB + (it + 3) * 32);
            cp_commit();
        }

        unsigned a[2][4], b[2][4];
#pragma unroll
        for (int mt = 0; mt < 2; mt++)
            ldsm4(a[mt][0], a[mt][1], a[mt][2], a[mt][3], aoff[mt] + sbase);
#pragma unroll
        for (int ntp = 0; ntp < 2; ntp++)
            ldsm4(b[ntp][0], b[ntp][1], b[ntp][2], b[ntp][3], boff[ntp] + sbase);
#pragma unroll
        for (int mt = 0; mt < 2; mt++)
#pragma unroll
            for (int nt = 0; nt < 4; nt++)
                mma_fp16(acc[mt][nt], a[mt], &b[nt >> 1][(nt & 1) * 2]);
    }

#pragma unroll
    for (int mt = 0; mt < 2; mt++) {
        int r = m0 + wm * 32 + mt * 16 + (lane >> 2);
#pragma unroll
        for (int nt = 0; nt < 4; nt++) {
            int c = n0 + wn * 32 + nt * 8 + 2 * (lane & 3);
            if (c < 300) {
                Cm[(size_t)r * 300 + c] = acc[mt][nt][0];
                if (c + 1 < 300) Cm[(size_t)r * 300 + c + 1] = acc[mt][nt][1];
                Cm[(size_t)(r + 8) * 300 + c] = acc[mt][nt][2];
                if (c + 1 < 300) Cm[(size_t)(r + 8) * 300 + c + 1] = acc[mt][nt][3];
            }
        }
    }
}

// ---------------- K4: combine (gate inline) -> ut fp32 + fp16, norms, zero att --------
// grid (2 l-chunks, B, 2 sides), 512 threads; gates for the 252-position window staged in smem.
__global__ __launch_bounds__(512) void k_comb(const float* __restrict__ udb,
                                              const float* __restrict__ idb,
                                              const float* __restrict__ wcb) {
    const int side = blockIdx.z;
    const int b = blockIdx.y;
    const int lbase = blockIdx.x * 250;
    const float* bias = side ? idb : udb;
    const float* Cb = g_C[side] + (size_t)b * Lsz * 300;
    const float* dots = g_dots[side] + (size_t)b * Lsz * 3;
    float* ut = g_ut[side] + (size_t)b * Lsz * Fsz;
    __half* utf = g_utf[side] + (size_t)b * Lsz * KA;

    __shared__ float sgv[252];
    const float wb = wcb[0];
    for (int i = threadIdx.x; i < 252; i += 512) {
        int l = lbase - 1 + i;
        float gv = 0.f;
        if (l >= 0 && l < Lsz) {
            float g = dots[l * 3 + 1] + wb;
            if (l >= 1)        g += dots[(l - 1) * 3 + 0];
            if (l <= Lsz - 2)  g += dots[(l + 1) * 3 + 2];
            gv = 1.f / (1.f + __expf(-g));
        }
        sgv[i] = gv;
    }
    __syncthreads();

    const int warp = threadIdx.x >> 5, lane = threadIdx.x & 31;
    for (int lo = warp; lo < 250; lo += 16) {
        const int l = lbase + lo;
        const float gm = sgv[lo];
        const float gc = sgv[lo + 1];
        const float gp = sgv[lo + 2];
        const float* c0 = Cb + (size_t)l * 300;
        float nr = 0.f;
#pragma unroll
        for (int itf = 0; itf < 4; itf++) {
            const int f = lane + itf * 32;
            float val = 0.f;
            if (f < Fsz) {
                val = bias[f] + gc * c0[Fsz + f];
                if (l >= 1)       val += gm * c0[f - 300];
                if (l < Lsz - 1)  val += gp * c0[300 + 2 * Fsz + f];
                ut[(size_t)l * Fsz + f] = val;
            }
            if (f < KA) {
                __half h = __float2half(val);
                utf[(size_t)l * KA + f] = h;
                float hv = __half2float(h);   // norm from ROUNDED value: consistent with mma
                nr += hv * hv;
            }
        }
        nr = warpSum(nr);
        if (lane == 0) {
            g_nrm[side][b * Lsz + l] = nr;
            g_att[side][b * Lsz + l] = 0.f;
        }
    }
}

// ---------------- K5: fp16 single-pass tensor-core pairwise attention ----------------
// smem: U @0 (64 x 240B), V @15360. 4 CTAs/SM.
__global__ __launch_bounds__(256, 4) void k_att_tc() {
    extern __shared__ __align__(16) unsigned char sm[];
    __shared__ float rsum[64], csum[64];
    const int b = blockIdx.z;
    const int l0 = blockIdx.x * 64, m0 = blockIdx.y * 64;
    const int tid = threadIdx.x;
    const int lane = tid & 31, wid = tid >> 5;
    const int wm2 = wid >> 2, wn2 = wid & 3;
    const unsigned sbase = s2u(&sm[0]);

    if (tid < 64) { rsum[tid] = 0.f; csum[tid] = 0.f; }

    // stage U and V tiles: 2 arrays x 64 rows x 14 chunks of 16B
    for (int i = tid; i < 2 * 64 * 14; i += 256) {
        int arr = i / 896;
        int rem = i - arr * 896;
        int r = rem / 14, c = rem - r * 14;
        int row = (arr ? m0 : l0) + r;
        bool valid = row < Lsz;
        int srow = valid ? row : 0;
        const __half* src = g_utf[arr] + ((size_t)(b * Lsz + srow)) * KA + c * 8;
        cp16z(sbase + arr * 15360 + r * 240 + c * 16, src, valid);
    }
    cp_commit();
    cp_wait<0>();
    __syncthreads();

    const int l4 = lane & 7, g4 = lane >> 3;
    unsigned aoff[2];
#pragma unroll
    for (int mt = 0; mt < 2; mt++) {
        int rowm = wm2 * 32 + mt * 16 + (g4 & 1) * 8 + l4;
        int koff = (g4 >> 1) * 8;
        aoff[mt] = sbase + (rowm * 120 + koff) * 2;
    }
    unsigned boffv;
    {
        int rown = wn2 * 16 + (g4 >> 1) * 8 + l4;
        int koff = (g4 & 1) * 8;
        boffv = sbase + 15360u + (rown * 120 + koff) * 2;
    }

    float acc[2][2][4];
#pragma unroll
    for (int i = 0; i < 2; i++)
#pragma unroll
        for (int j = 0; j < 2; j++)
#pragma unroll
            for (int q = 0; q < 4; q++) acc[i][j][q] = 0.f;

#pragma unroll
    for (int ck = 0; ck < 7; ck++) {
        const unsigned kb = ck * 32;
        unsigned a[2][4], bfr[4];
#pragma unroll
        for (int mt = 0; mt < 2; mt++)
            ldsm4(a[mt][0], a[mt][1], a[mt][2], a[mt][3], aoff[mt] + kb);
        ldsm4(bfr[0], bfr[1], bfr[2], bfr[3], boffv + kb);
#pragma unroll
        for (int mt = 0; mt < 2; mt++)
#pragma unroll
            for (int nt = 0; nt < 2; nt++)
                mma_fp16(acc[mt][nt], a[mt], &bfr[nt * 2]);
    }

    float nu[2][2], nv[2][2];
#pragma unroll
    for (int mt = 0; mt < 2; mt++)
#pragma unroll
        for (int h = 0; h < 2; h++) {
            int l = l0 + wm2 * 32 + mt * 16 + h * 8 + (lane >> 2);
            nu[mt][h] = (l < Lsz) ? g_nrm[0][b * Lsz + l] : 0.f;
        }
#pragma unroll
    for (int nt = 0; nt < 2; nt++)
#pragma unroll
        for (int cc = 0; cc < 2; cc++) {
            int m = m0 + wn2 * 16 + nt * 8 + 2 * (lane & 3) + cc;
            nv[nt][cc] = (m < Lsz) ? g_nrm[1][b * Lsz + m] : 0.f;
        }

    float rsv[4] = {0, 0, 0, 0}, csv[4] = {0, 0, 0, 0};
#pragma unroll
    for (int mt = 0; mt < 2; mt++)
#pragma unroll
        for (int nt = 0; nt < 2; nt++)
#pragma unroll
            for (int q = 0; q < 4; q++) {
                int h = q >> 1, cc = q & 1;
                int l = l0 + wm2 * 32 + mt * 16 + h * 8 + (lane >> 2);
                int m = m0 + wn2 * 16 + nt * 8 + 2 * (lane & 3) + cc;
                if (l < Lsz && m < Lsz) {
                    float sq = nu[mt][h] + nv[nt][cc] - 2.f * acc[mt][nt][q];
                    float a = 1.f / (1.f + sqrtf(fmaxf(sq, 1e-12f)));
                    rsv[mt * 2 + h] += a;
                    csv[nt * 2 + cc] += a;
                }
            }
#pragma unroll
    for (int q = 0; q < 4; q++) {
        atomicAdd(&rsum[wm2 * 32 + (q >> 1) * 16 + (q & 1) * 8 + (lane >> 2)], rsv[q]);
        atomicAdd(&csum[wn2 * 16 + (q >> 1) * 8 + 2 * (lane & 3) + (q & 1)], csv[q]);
    }
    __syncthreads();
    if (tid < 64) {
        if (l0 + tid < Lsz) atomicAdd(&g_att[0][b * Lsz + l0 + tid], rsum[tid]);
        if (m0 + tid < Lsz) atomicAdd(&g_att[1][b * Lsz + m0 + tid], csum[tid]);
    }
}

// ---------------- K6: pooling + FC head + id-emb gather ----------------
__global__ void k_head(const float* __restrict__ uacw, const float* __restrict__ uacb,
                       const float* __restrict__ iacw, const float* __restrict__ iacb,
                       const float* __restrict__ ufw,  const float* __restrict__ ufb,
                       const float* __restrict__ ifw,  const float* __restrict__ ifb,
                       const int* __restrict__ uids,   const int* __restrict__ iids,
                       const float* __restrict__ uide, const float* __restrict__ iide,
                       float* __restrict__ out) {
    int b = blockIdx.x;
    int side = blockIdx.y;
    const float* ut  = g_ut[side] + (size_t)b * Lsz * Fsz;
    const float* att = g_att[side] + b * Lsz;
    const float* acw = side ? iacw : uacw;
    const float* acb = side ? iacb : uacb;
    const float* fw  = side ? ifw : ufw;
    const float* fb  = side ? ifb : ufb;
    __shared__ float S[3][Fsz];
    __shared__ float am[Fsz];
    int t = threadIdx.x;

    if (t < Fsz) {
        float s0 = 0.f, s1 = 0.f, s2 = 0.f;
        float pm = 0.f;
        float pc = ut[t] * att[0];
        for (int l = 0; l < Lsz; l++) {
            float pn = (l + 1 < Lsz) ? ut[(l + 1) * Fsz + t] * att[l + 1] : 0.f;
            float s = pm + pc + pn;
            if (l <= Lsz - 3)           s0 += s;
            if (l >= 1 && l <= Lsz - 2) s1 += s;
            if (l >= 2)                 s2 += s;
            pm = pc; pc = pn;
        }
        S[0][t] = s0; S[1][t] = s1; S[2][t] = s2;
    }
    __syncthreads();
    if (t < Fsz) {
        float a = 0.f;
#pragma unroll
        for (int k = 0; k < 3; k++)
            for (int g = 0; g < Fsz; g++)
                a += S[k][g] * acw[(t * 3 + k) * Fsz + g];
        am[t] = acb[t] + a * (1.f / (float)(Lsz - 2));
    }
    __syncthreads();
    if (t < IDs) {
        float o = fb[t];
        for (int f = 0; f < Fsz; f++) o += am[f] * fw[t * Fsz + f];
        o = fmaxf(o, 0.f);
        int base = side ? (Bsz * 2 * IDs) : 0;
        out[base + (b * 2 + 0) * IDs + t] = o;
    }
    if (t >= 64 && t < 64 + IDs) {
        int i = t - 64;
        if (side == 0) {
            out[(b * 2 + 1) * IDs + i] = iide[(size_t)iids[b] * IDs + i];
        } else {
            out[Bsz * 2 * IDs + (b * 2 + 1) * IDs + i] = uide[(size_t)uids[b] * IDs + i];
        }
    }
}

// ---------------- launch ----------------
extern "C" void kernel_launch(void* const* d_in, const int* in_sizes, int n_in,
                              void* d_out, int out_size) {
    const int*   uids = (const int*)d_in[0];
    const int*   iids = (const int*)d_in[1];
    const int*   udoc = (const int*)d_in[2];
    const int*   idoc = (const int*)d_in[3];
    const float* uemb = (const float*)d_in[4];
    const float* iemb = (const float*)d_in[5];
    const float* wcw  = (const float*)d_in[6];
    const float* wcb  = (const float*)d_in[7];
    const float* udcw = (const float*)d_in[8];
    const float* udcb = (const float*)d_in[9];
    const float* idcw = (const float*)d_in[10];
    const float* idcb = (const float*)d_in[11];
    const float* uacw = (const float*)d_in[12];
    const float* uacb = (const float*)d_in[13];
    const float* iacw = (const float*)d_in[14];
    const float* iacb = (const float*)d_in[15];
    const float* ufw  = (const float*)d_in[16];
    const float* ufb  = (const float*)d_in[17];
    const float* ifw  = (const float*)d_in[18];
    const float* ifb  = (const float*)d_in[19];
    const float* uide = (const float*)d_in[20];
    const float* iide = (const float*)d_in[21];
    float* out = (float*)d_out;

    cudaFuncSetAttribute(k_gemm_fp16, cudaFuncAttributeMaxDynamicSharedMemorySize, 4 * (int)STG_G);
    cudaFuncSetAttribute(k_att_tc,    cudaFuncAttributeMaxDynamicSharedMemorySize, 2 * 15360);

    k_prep<<<(2 * KP * KP + 255) / 256, 256>>>(udcw, idcw);
    dim3 gBL(BL, 2);
    k_gather<<<gBL, 128>>>(udoc, idoc, uemb, iemb, wcw);
    k_gemm_fp16<<<dim3(5, 250, 2), 256, 4 * STG_G>>>();
    k_comb<<<dim3(2, Bsz, 2), 512>>>(udcb, idcb, wcb);
    k_att_tc<<<dim3(8, 8, Bsz), 256, 2 * 15360>>>();
    k_head<<<dim3(Bsz, 2), 128>>>(uacw, uacb, iacw, iacb, ufw, ufb, ifw, ifb,
                                  uids, iids, uide, iide, out);
}

// round 13
// speedup vs baseline: 1.6977x; 1.2811x over previous
#include <cuda_runtime.h>
#include <cuda_bf16.h>
#include <cuda_fp16.h>

#define Bsz 64
#define Lsz 500
#define Dsz 300
#define Fsz 100
#define IDs 32
#define BL  (Bsz*Lsz)   // 32000
#define KP  320         // padded K (and padded N) for the doc GEMM
#define NK  20          // KP / 16 k-iterations
#define KA  112         // padded F for the attention GEMM (7 x 16)
#define STG_G 9216u     // gemm smem stage: A 128x48B + B 64x48B

// ---------------- scratch (static device globals; no allocation) ----------------
__device__ __align__(16) __half g_A[2][BL*KP];    // gathered emb, fp16, ungated
__device__ __align__(16) __half g_W[2][KP*KP];    // doc-conv weights fp16, [n][k]
__device__ float g_dots[2][BL*3];
__device__ float g_C[2][BL*300];
__device__ __align__(16) __half g_utf[2][BL*KA];  // conv feature fp16 (att + head)
__device__ float g_nrm[2][BL];
__device__ float g_att[2][BL];

__device__ __forceinline__ float warpSum(float v) {
#pragma unroll
    for (int o = 16; o; o >>= 1) v += __shfl_down_sync(0xffffffffu, v, o);
    return v;
}

__device__ __forceinline__ void ldsm4(unsigned& r0, unsigned& r1,
                                      unsigned& r2, unsigned& r3, unsigned addr) {
    asm volatile("ldmatrix.sync.aligned.m8n8.x4.shared.b16 {%0,%1,%2,%3}, [%4];"
                 : "=r"(r0), "=r"(r1), "=r"(r2), "=r"(r3) : "r"(addr));
}

__device__ __forceinline__ void mma_fp16(float* c, const unsigned* a, const unsigned* b) {
    asm volatile(
        "mma.sync.aligned.m16n8k16.row.col.f32.f16.f16.f32 "
        "{%0,%1,%2,%3}, {%4,%5,%6,%7}, {%8,%9}, {%0,%1,%2,%3};\n"
        : "+f"(c[0]), "+f"(c[1]), "+f"(c[2]), "+f"(c[3])
        : "r"(a[0]), "r"(a[1]), "r"(a[2]), "r"(a[3]), "r"(b[0]), "r"(b[1]));
}

__device__ __forceinline__ void cp16(unsigned sdst, const void* gsrc) {
    asm volatile("cp.async.cg.shared.global [%0], [%1], 16;" :: "r"(sdst), "l"(gsrc));
}
__device__ __forceinline__ void cp16z(unsigned sdst, const void* gsrc, bool v) {
    int sz = v ? 16 : 0;
    asm volatile("cp.async.cg.shared.global [%0], [%1], 16, %2;" :: "r"(sdst), "l"(gsrc), "r"(sz));
}
__device__ __forceinline__ void cp_commit() { asm volatile("cp.async.commit_group;"); }
template <int N>
__device__ __forceinline__ void cp_wait() { asm volatile("cp.async.wait_group %0;" :: "n"(N)); }

__device__ __forceinline__ unsigned s2u(const void* p) {
    unsigned a;
    asm("{ .reg .u64 t; cvta.to.shared.u64 t, %1; cvt.u32.u64 %0, t; }" : "=r"(a) : "l"(p));
    return a;
}

// ---------------- K0: repack doc-conv weights fp16 -> [n][k] padded ----------------
__global__ void k_prep(const float* __restrict__ uw, const float* __restrict__ iw) {
    int idx = blockIdx.x * 256 + threadIdx.x;
    if (idx >= 2 * KP * KP) return;
    int side = idx / (KP * KP);
    int r = idx - side * KP * KP;
    int n = r / KP, k = r % KP;
    float x = 0.f;
    if (n < 300 && k < 300) {
        int f = n % Fsz, ks = n / Fsz;
        const float* w = side ? iw : uw;
        x = w[(f * 3 + ks) * Dsz + k];
    }
    g_W[side][n * KP + k] = __float2half(x);
}

// ---------------- K1: gather + word-gate dots + fp16 convert (ungated) ----------------
__global__ void k_gather(const int* __restrict__ udoc, const int* __restrict__ idoc,
                         const float* __restrict__ uemb, const float* __restrict__ iemb,
                         const float* __restrict__ wc) {
    int side = blockIdx.y;
    int bl = blockIdx.x;
    const int* doc = side ? idoc : udoc;
    const float* emb = side ? iemb : uemb;
    int row = doc[bl];
    const float* e = emb + (size_t)row * Dsz;
    unsigned* ad = reinterpret_cast<unsigned*>(&g_A[side][(size_t)bl * KP]);
    float p0 = 0.f, p1 = 0.f, p2 = 0.f;
    for (int p = threadIdx.x; p < KP / 2; p += 128) {
        int d = 2 * p;
        float x0 = 0.f, x1 = 0.f;
        if (d < 300) {
            float2 v = *reinterpret_cast<const float2*>(&e[d]);
            x0 = v.x; x1 = v.y;
            p0 += x0 * wc[d]       + x1 * wc[d + 1];
            p1 += x0 * wc[300 + d] + x1 * wc[301 + d];
            p2 += x0 * wc[600 + d] + x1 * wc[601 + d];
        }
        __half h0 = __float2half(x0);
        __half h1 = __float2half(x1);
        ad[p] = (unsigned)__half_as_ushort(h0) | ((unsigned)__half_as_ushort(h1) << 16);
    }
    __shared__ float sh[3][4];
    p0 = warpSum(p0); p1 = warpSum(p1); p2 = warpSum(p2);
    int lane = threadIdx.x & 31, w = threadIdx.x >> 5;
    if (lane == 0) { sh[0][w] = p0; sh[1][w] = p1; sh[2][w] = p2; }
    __syncthreads();
    if (threadIdx.x == 0) {
        g_dots[side][bl * 3 + 0] = sh[0][0] + sh[0][1] + sh[0][2] + sh[0][3];
        g_dots[side][bl * 3 + 1] = sh[1][0] + sh[1][1] + sh[1][2] + sh[1][3];
        g_dots[side][bl * 3 + 2] = sh[2][0] + sh[2][1] + sh[2][2] + sh[2][3];
    }
}

// ---------------- K3: fp16 single-pass mma GEMM (32000x320)@(320x320) ----------------
__global__ __launch_bounds__(256, 3) void k_gemm_fp16() {
    const int side = blockIdx.z;
    float* __restrict__ Cm = g_C[side];

    extern __shared__ __align__(16) unsigned char smbuf[];   // 4 x 9216

    const int tid = threadIdx.x;
    const int lane = tid & 31, wid = tid >> 5;
    const int wm = wid >> 1, wn = wid & 1;
    const int n0 = blockIdx.x * 64;
    const int m0 = blockIdx.y * 128;

    const unsigned smem0 = s2u(&smbuf[0]);

    const int arow = tid >> 1, ahalf = tid & 1;
    const char* gA = (const char*)&g_A[side][((size_t)(m0 + arow)) * KP + ahalf * 8];
    const unsigned sA = smem0 + arow * 48 + ahalf * 16;
    const int brow = tid >> 1;
    const char* gB = (const char*)&g_W[side][((size_t)(n0 + (brow & 63))) * KP + ahalf * 8];
    const unsigned sB = smem0 + 6144u + (brow & 63) * 48 + ahalf * 16;
    const bool hasB = tid < 128;

    float acc[2][4][4];
#pragma unroll
    for (int i = 0; i < 2; i++)
#pragma unroll
        for (int j = 0; j < 4; j++)
#pragma unroll
            for (int q = 0; q < 4; q++) acc[i][j][q] = 0.f;

#pragma unroll
    for (int s = 0; s < 3; s++) {
        cp16(sA + s * STG_G, gA + s * 32);
        if (hasB) cp16(sB + s * STG_G, gB + s * 32);
        cp_commit();
    }

    const int l4 = lane & 7, g4 = lane >> 3;
    unsigned aoff[2];
#pragma unroll
    for (int mt = 0; mt < 2; mt++) {
        int rowm = wm * 32 + mt * 16 + (g4 & 1) * 8 + l4;
        aoff[mt] = smem0 + rowm * 48 + (g4 >> 1) * 16;
    }
    unsigned boff[2];
#pragma unroll
    for (int ntp = 0; ntp < 2; ntp++) {
        int rown = wn * 32 + ntp * 16 + (g4 >> 1) * 8 + l4;
        boff[ntp] = smem0 + 6144u + rown * 48 + (g4 & 1) * 16;
    }

    for (int it = 0; it < NK; it++) {
        const unsigned sbase = (unsigned)(it & 3) * STG_G;
        if (it < NK - 3) cp_wait<2>(); else cp_wait<0>();
        __syncthreads();

        if (it + 3 < NK) {
            const unsigned nb = (unsigned)((it + 3) & 3) * STG_G;
            cp16(sA + nb, gA + (it + 3) * 32);
            if (hasB) cp16(sB + nb, gB + (it + 3) * 32);
            cp_commit();
        }

        unsigned a[2][4], b[2][4];
#pragma unroll
        for (int mt = 0; mt < 2; mt++)
            ldsm4(a[mt][0], a[mt][1], a[mt][2], a[mt][3], aoff[mt] + sbase);
#pragma unroll
        for (int ntp = 0; ntp < 2; ntp++)
            ldsm4(b[ntp][0], b[ntp][1], b[ntp][2], b[ntp][3], boff[ntp] + sbase);
#pragma unroll
        for (int mt = 0; mt < 2; mt++)
#pragma unroll
            for (int nt = 0; nt < 4; nt++)
                mma_fp16(acc[mt][nt], a[mt], &b[nt >> 1][(nt & 1) * 2]);
    }

#pragma unroll
    for (int mt = 0; mt < 2; mt++) {
        int r = m0 + wm * 32 + mt * 16 + (lane >> 2);
#pragma unroll
        for (int nt = 0; nt < 4; nt++) {
            int c = n0 + wn * 32 + nt * 8 + 2 * (lane & 3);
            if (c < 300) {
                Cm[(size_t)r * 300 + c] = acc[mt][nt][0];
                if (c + 1 < 300) Cm[(size_t)r * 300 + c + 1] = acc[mt][nt][1];
                Cm[(size_t)(r + 8) * 300 + c] = acc[mt][nt][2];
                if (c + 1 < 300) Cm[(size_t)(r + 8) * 300 + c + 1] = acc[mt][nt][3];
            }
        }
    }
}

// ---------------- K4: combine (gate inline) -> utf fp16, norms, zero att --------------
// grid (16 l-chunks, B, 2 sides), 256 threads = 8 warps; warp-per-position, 4 positions/warp.
// Lanes own f-PAIRS so the fp16 store is one packed 4B write.
__global__ __launch_bounds__(256) void k_comb(const float* __restrict__ udb,
                                              const float* __restrict__ idb,
                                              const float* __restrict__ wcb) {
    const int side = blockIdx.z;
    const int b = blockIdx.y;
    const int lbase = blockIdx.x * 32;
    const float* bias = side ? idb : udb;
    const float* Cb = g_C[side] + (size_t)b * Lsz * 300;
    const float* dots = g_dots[side] + (size_t)b * Lsz * 3;
    __half* utf = g_utf[side] + (size_t)b * Lsz * KA;

    __shared__ float sgv[34];   // gates for l in [lbase-1, lbase+32]
    const float wb = wcb[0];
    if (threadIdx.x < 34) {
        int l = lbase - 1 + threadIdx.x;
        float gv = 0.f;
        if (l >= 0 && l < Lsz) {
            float g = dots[l * 3 + 1] + wb;
            if (l >= 1)        g += dots[(l - 1) * 3 + 0];
            if (l <= Lsz - 2)  g += dots[(l + 1) * 3 + 2];
            gv = 1.f / (1.f + __expf(-g));
        }
        sgv[threadIdx.x] = gv;
    }
    __syncthreads();

    const int warp = threadIdx.x >> 5, lane = threadIdx.x & 31;
#pragma unroll
    for (int po = 0; po < 4; po++) {
        const int lo = po * 8 + warp;
        const int l = lbase + lo;
        if (l >= Lsz) break;
        const float gm = sgv[lo];
        const float gc = sgv[lo + 1];
        const float gp = sgv[lo + 2];
        const float* c0 = Cb + (size_t)l * 300;
        unsigned* urow = reinterpret_cast<unsigned*>(utf + (size_t)l * KA);
        float nr = 0.f;
#pragma unroll
        for (int half = 0; half < 2; half++) {
            const int f0 = half * 64 + 2 * lane;
            float v0 = 0.f, v1 = 0.f;
            if (f0 < Fsz) {
                v0 = bias[f0] + gc * c0[Fsz + f0];
                if (l >= 1)       v0 += gm * c0[f0 - 300];
                if (l < Lsz - 1)  v0 += gp * c0[300 + 2 * Fsz + f0];
            }
            if (f0 + 1 < Fsz) {
                v1 = bias[f0 + 1] + gc * c0[Fsz + f0 + 1];
                if (l >= 1)       v1 += gm * c0[f0 + 1 - 300];
                if (l < Lsz - 1)  v1 += gp * c0[300 + 2 * Fsz + f0 + 1];
            }
            __half h0 = __float2half(v0);
            __half h1 = __float2half(v1);
            if (f0 < KA)
                urow[half * 32 + lane] =
                    (unsigned)__half_as_ushort(h0) | ((unsigned)__half_as_ushort(h1) << 16);
            float g0 = __half2float(h0), g1 = __half2float(h1);
            nr += g0 * g0 + g1 * g1;   // norm from ROUNDED values: consistent with mma
        }
        nr = warpSum(nr);
        if (lane == 0) {
            g_nrm[side][b * Lsz + l] = nr;
            g_att[side][b * Lsz + l] = 0.f;
        }
    }
}

// ---------------- K5: fp16 single-pass tensor-core pairwise attention ----------------
__global__ __launch_bounds__(256, 4) void k_att_tc() {
    extern __shared__ __align__(16) unsigned char sm[];
    __shared__ float rsum[64], csum[64];
    const int b = blockIdx.z;
    const int l0 = blockIdx.x * 64, m0 = blockIdx.y * 64;
    const int tid = threadIdx.x;
    const int lane = tid & 31, wid = tid >> 5;
    const int wm2 = wid >> 2, wn2 = wid & 3;
    const unsigned sbase = s2u(&sm[0]);

    if (tid < 64) { rsum[tid] = 0.f; csum[tid] = 0.f; }

    for (int i = tid; i < 2 * 64 * 14; i += 256) {
        int arr = i / 896;
        int rem = i - arr * 896;
        int r = rem / 14, c = rem - r * 14;
        int row = (arr ? m0 : l0) + r;
        bool valid = row < Lsz;
        int srow = valid ? row : 0;
        const __half* src = g_utf[arr] + ((size_t)(b * Lsz + srow)) * KA + c * 8;
        cp16z(sbase + arr * 15360 + r * 240 + c * 16, src, valid);
    }
    cp_commit();
    cp_wait<0>();
    __syncthreads();

    const int l4 = lane & 7, g4 = lane >> 3;
    unsigned aoff[2];
#pragma unroll
    for (int mt = 0; mt < 2; mt++) {
        int rowm = wm2 * 32 + mt * 16 + (g4 & 1) * 8 + l4;
        int koff = (g4 >> 1) * 8;
        aoff[mt] = sbase + (rowm * 120 + koff) * 2;
    }
    unsigned boffv;
    {
        int rown = wn2 * 16 + (g4 >> 1) * 8 + l4;
        int koff = (g4 & 1) * 8;
        boffv = sbase + 15360u + (rown * 120 + koff) * 2;
    }

    float acc[2][2][4];
#pragma unroll
    for (int i = 0; i < 2; i++)
#pragma unroll
        for (int j = 0; j < 2; j++)
#pragma unroll
            for (int q = 0; q < 4; q++) acc[i][j][q] = 0.f;

#pragma unroll
    for (int ck = 0; ck < 7; ck++) {
        const unsigned kb = ck * 32;
        unsigned a[2][4], bfr[4];
#pragma unroll
        for (int mt = 0; mt < 2; mt++)
            ldsm4(a[mt][0], a[mt][1], a[mt][2], a[mt][3], aoff[mt] + kb);
        ldsm4(bfr[0], bfr[1], bfr[2], bfr[3], boffv + kb);
#pragma unroll
        for (int mt = 0; mt < 2; mt++)
#pragma unroll
            for (int nt = 0; nt < 2; nt++)
                mma_fp16(acc[mt][nt], a[mt], &bfr[nt * 2]);
    }

    float nu[2][2], nv[2][2];
#pragma unroll
    for (int mt = 0; mt < 2; mt++)
#pragma unroll
        for (int h = 0; h < 2; h++) {
            int l = l0 + wm2 * 32 + mt * 16 + h * 8 + (lane >> 2);
            nu[mt][h] = (l < Lsz) ? g_nrm[0][b * Lsz + l] : 0.f;
        }
#pragma unroll
    for (int nt = 0; nt < 2; nt++)
#pragma unroll
        for (int cc = 0; cc < 2; cc++) {
            int m = m0 + wn2 * 16 + nt * 8 + 2 * (lane & 3) + cc;
            nv[nt][cc] = (m < Lsz) ? g_nrm[1][b * Lsz + m] : 0.f;
        }

    float rsv[4] = {0, 0, 0, 0}, csv[4] = {0, 0, 0, 0};
#pragma unroll
    for (int mt = 0; mt < 2; mt++)
#pragma unroll
        for (int nt = 0; nt < 2; nt++)
#pragma unroll
            for (int q = 0; q < 4; q++) {
                int h = q >> 1, cc = q & 1;
                int l = l0 + wm2 * 32 + mt * 16 + h * 8 + (lane >> 2);
                int m = m0 + wn2 * 16 + nt * 8 + 2 * (lane & 3) + cc;
                if (l < Lsz && m < Lsz) {
                    float sq = nu[mt][h] + nv[nt][cc] - 2.f * acc[mt][nt][q];
                    float a = 1.f / (1.f + sqrtf(fmaxf(sq, 1e-12f)));
                    rsv[mt * 2 + h] += a;
                    csv[nt * 2 + cc] += a;
                }
            }
#pragma unroll
    for (int q = 0; q < 4; q++) {
        atomicAdd(&rsum[wm2 * 32 + (q >> 1) * 16 + (q & 1) * 8 + (lane >> 2)], rsv[q]);
        atomicAdd(&csum[wn2 * 16 + (q >> 1) * 8 + 2 * (lane & 3) + (q & 1)], csv[q]);
    }
    __syncthreads();
    if (tid < 64) {
        if (l0 + tid < Lsz) atomicAdd(&g_att[0][b * Lsz + l0 + tid], rsum[tid]);
        if (m0 + tid < Lsz) atomicAdd(&g_att[1][b * Lsz + m0 + tid], csum[tid]);
    }
}

// ---------------- K6: pooling + FC head + id-emb gather (reads fp16 utf) -------------
__global__ void k_head(const float* __restrict__ uacw, const float* __restrict__ uacb,
                       const float* __restrict__ iacw, const float* __restrict__ iacb,
                       const float* __restrict__ ufw,  const float* __restrict__ ufb,
                       const float* __restrict__ ifw,  const float* __restrict__ ifb,
                       const int* __restrict__ uids,   const int* __restrict__ iids,
                       const float* __restrict__ uide, const float* __restrict__ iide,
                       float* __restrict__ out) {
    int b = blockIdx.x;
    int side = blockIdx.y;
    const __half* ut = g_utf[side] + (size_t)b * Lsz * KA;
    const float* att = g_att[side] + b * Lsz;
    const float* acw = side ? iacw : uacw;
    const float* acb = side ? iacb : uacb;
    const float* fw  = side ? ifw : ufw;
    const float* fb  = side ? ifb : ufb;
    __shared__ float S[3][Fsz];
    __shared__ float am[Fsz];
    int t = threadIdx.x;

    if (t < Fsz) {
        float s0 = 0.f, s1 = 0.f, s2 = 0.f;
        float pm = 0.f;
        float pc = __half2float(ut[t]) * att[0];
        for (int l = 0; l < Lsz; l++) {
            float pn = (l + 1 < Lsz) ? __half2float(ut[(size_t)(l + 1) * KA + t]) * att[l + 1] : 0.f;
            float s = pm + pc + pn;
            if (l <= Lsz - 3)           s0 += s;
            if (l >= 1 && l <= Lsz - 2) s1 += s;
            if (l >= 2)                 s2 += s;
            pm = pc; pc = pn;
        }
        S[0][t] = s0; S[1][t] = s1; S[2][t] = s2;
    }
    __syncthreads();
    if (t < Fsz) {
        float a = 0.f;
#pragma unroll
        for (int k = 0; k < 3; k++)
            for (int g = 0; g < Fsz; g++)
                a += S[k][g] * acw[(t * 3 + k) * Fsz + g];
        am[t] = acb[t] + a * (1.f / (float)(Lsz - 2));
    }
    __syncthreads();
    if (t < IDs) {
        float o = fb[t];
        for (int f = 0; f < Fsz; f++) o += am[f] * fw[t * Fsz + f];
        o = fmaxf(o, 0.f);
        int base = side ? (Bsz * 2 * IDs) : 0;
        out[base + (b * 2 + 0) * IDs + t] = o;
    }
    if (t >= 64 && t < 64 + IDs) {
        int i = t - 64;
        if (side == 0) {
            out[(b * 2 + 1) * IDs + i] = iide[(size_t)iids[b] * IDs + i];
        } else {
            out[Bsz * 2 * IDs + (b * 2 + 1) * IDs + i] = uide[(size_t)uids[b] * IDs + i];
        }
    }
}

// ---------------- launch ----------------
extern "C" void kernel_launch(void* const* d_in, const int* in_sizes, int n_in,
                              void* d_out, int out_size) {
    const int*   uids = (const int*)d_in[0];
    const int*   iids = (const int*)d_in[1];
    const int*   udoc = (const int*)d_in[2];
    const int*   idoc = (const int*)d_in[3];
    const float* uemb = (const float*)d_in[4];
    const float* iemb = (const float*)d_in[5];
    const float* wcw  = (const float*)d_in[6];
    const float* wcb  = (const float*)d_in[7];
    const float* udcw = (const float*)d_in[8];
    const float* udcb = (const float*)d_in[9];
    const float* idcw = (const float*)d_in[10];
    const float* idcb = (const float*)d_in[11];
    const float* uacw = (const float*)d_in[12];
    const float* uacb = (const float*)d_in[13];
    const float* iacw = (const float*)d_in[14];
    const float* iacb = (const float*)d_in[15];
    const float* ufw  = (const float*)d_in[16];
    const float* ufb  = (const float*)d_in[17];
    const float* ifw  = (const float*)d_in[18];
    const float* ifb  = (const float*)d_in[19];
    const float* uide = (const float*)d_in[20];
    const float* iide = (const float*)d_in[21];
    float* out = (float*)d_out;

    cudaFuncSetAttribute(k_gemm_fp16, cudaFuncAttributeMaxDynamicSharedMemorySize, 4 * (int)STG_G);
    cudaFuncSetAttribute(k_att_tc,    cudaFuncAttributeMaxDynamicSharedMemorySize, 2 * 15360);

    k_prep<<<(2 * KP * KP + 255) / 256, 256>>>(udcw, idcw);
    dim3 gBL(BL, 2);
    k_gather<<<gBL, 128>>>(udoc, idoc, uemb, iemb, wcw);
    k_gemm_fp16<<<dim3(5, 250, 2), 256, 4 * STG_G>>>();
    k_comb<<<dim3(16, Bsz, 2), 256>>>(udcb, idcb, wcb);
    k_att_tc<<<dim3(8, 8, Bsz), 256, 2 * 15360>>>();
    k_head<<<dim3(Bsz, 2), 128>>>(uacw, uacb, iacw, iacb, ufw, ufb, ifw, ifb,
                                  uids, iids, uide, iide, out);
}

// round 14
// speedup vs baseline: 1.8520x; 1.0909x over previous
#include <cuda_runtime.h>
#include <cuda_bf16.h>
#include <cuda_fp16.h>

#define Bsz 64
#define Lsz 500
#define Dsz 300
#define Fsz 100
#define IDs 32
#define BL  (Bsz*Lsz)   // 32000
#define KP  320         // padded K (and padded N) for the doc GEMM
#define NK  20          // KP / 16 k-iterations
#define KA  112         // padded F for the attention GEMM (7 x 16)
#define STG_G 9216u     // gemm smem stage: A 128x48B + B 64x48B

// ---------------- scratch (static device globals; no allocation) ----------------
__device__ __align__(16) __half g_A[2][BL*KP];    // gathered emb, fp16, ungated
__device__ __align__(16) __half g_W[2][KP*KP];    // doc-conv weights fp16, [n][k]
__device__ float g_dots[2][BL*3];
__device__ __align__(16) __half g_C[2][BL*300];   // GEMM out, fp16 packed
__device__ __align__(16) __half g_utf[2][BL*KA];  // conv feature fp16 (att + head)
__device__ float g_nrm[2][BL];
__device__ float g_att[2][BL];

__device__ __forceinline__ float warpSum(float v) {
#pragma unroll
    for (int o = 16; o; o >>= 1) v += __shfl_down_sync(0xffffffffu, v, o);
    return v;
}

__device__ __forceinline__ void ldsm4(unsigned& r0, unsigned& r1,
                                      unsigned& r2, unsigned& r3, unsigned addr) {
    asm volatile("ldmatrix.sync.aligned.m8n8.x4.shared.b16 {%0,%1,%2,%3}, [%4];"
                 : "=r"(r0), "=r"(r1), "=r"(r2), "=r"(r3) : "r"(addr));
}

__device__ __forceinline__ void mma_fp16(float* c, const unsigned* a, const unsigned* b) {
    asm volatile(
        "mma.sync.aligned.m16n8k16.row.col.f32.f16.f16.f32 "
        "{%0,%1,%2,%3}, {%4,%5,%6,%7}, {%8,%9}, {%0,%1,%2,%3};\n"
        : "+f"(c[0]), "+f"(c[1]), "+f"(c[2]), "+f"(c[3])
        : "r"(a[0]), "r"(a[1]), "r"(a[2]), "r"(a[3]), "r"(b[0]), "r"(b[1]));
}

__device__ __forceinline__ void cp16(unsigned sdst, const void* gsrc) {
    asm volatile("cp.async.cg.shared.global [%0], [%1], 16;" :: "r"(sdst), "l"(gsrc));
}
__device__ __forceinline__ void cp16z(unsigned sdst, const void* gsrc, bool v) {
    int sz = v ? 16 : 0;
    asm volatile("cp.async.cg.shared.global [%0], [%1], 16, %2;" :: "r"(sdst), "l"(gsrc), "r"(sz));
}
__device__ __forceinline__ void cp_commit() { asm volatile("cp.async.commit_group;"); }
template <int N>
__device__ __forceinline__ void cp_wait() { asm volatile("cp.async.wait_group %0;" :: "n"(N)); }

__device__ __forceinline__ unsigned s2u(const void* p) {
    unsigned a;
    asm("{ .reg .u64 t; cvta.to.shared.u64 t, %1; cvt.u32.u64 %0, t; }" : "=r"(a) : "l"(p));
    return a;
}

__device__ __forceinline__ unsigned packh(float a, float b) {
    __half ha = __float2half(a), hb = __float2half(b);
    return (unsigned)__half_as_ushort(ha) | ((unsigned)__half_as_ushort(hb) << 16);
}

// ---------------- K0: repack doc-conv weights fp16 -> [n][k] padded ----------------
__global__ void k_prep(const float* __restrict__ uw, const float* __restrict__ iw) {
    int idx = blockIdx.x * 256 + threadIdx.x;
    if (idx >= 2 * KP * KP) return;
    int side = idx / (KP * KP);
    int r = idx - side * KP * KP;
    int n = r / KP, k = r % KP;
    float x = 0.f;
    if (n < 300 && k < 300) {
        int f = n % Fsz, ks = n / Fsz;
        const float* w = side ? iw : uw;
        x = w[(f * 3 + ks) * Dsz + k];
    }
    g_W[side][n * KP + k] = __float2half(x);
}

// ---------------- K1: gather + word-gate dots + fp16 convert (ungated) ----------------
__global__ void k_gather(const int* __restrict__ udoc, const int* __restrict__ idoc,
                         const float* __restrict__ uemb, const float* __restrict__ iemb,
                         const float* __restrict__ wc) {
    int side = blockIdx.y;
    int bl = blockIdx.x;
    const int* doc = side ? idoc : udoc;
    const float* emb = side ? iemb : uemb;
    int row = doc[bl];
    const float* e = emb + (size_t)row * Dsz;
    unsigned* ad = reinterpret_cast<unsigned*>(&g_A[side][(size_t)bl * KP]);
    float p0 = 0.f, p1 = 0.f, p2 = 0.f;
    for (int p = threadIdx.x; p < KP / 2; p += 128) {
        int d = 2 * p;
        float x0 = 0.f, x1 = 0.f;
        if (d < 300) {
            float2 v = *reinterpret_cast<const float2*>(&e[d]);
            x0 = v.x; x1 = v.y;
            p0 += x0 * wc[d]       + x1 * wc[d + 1];
            p1 += x0 * wc[300 + d] + x1 * wc[301 + d];
            p2 += x0 * wc[600 + d] + x1 * wc[601 + d];
        }
        ad[p] = packh(x0, x1);
    }
    __shared__ float sh[3][4];
    p0 = warpSum(p0); p1 = warpSum(p1); p2 = warpSum(p2);
    int lane = threadIdx.x & 31, w = threadIdx.x >> 5;
    if (lane == 0) { sh[0][w] = p0; sh[1][w] = p1; sh[2][w] = p2; }
    __syncthreads();
    if (threadIdx.x == 0) {
        g_dots[side][bl * 3 + 0] = sh[0][0] + sh[0][1] + sh[0][2] + sh[0][3];
        g_dots[side][bl * 3 + 1] = sh[1][0] + sh[1][1] + sh[1][2] + sh[1][3];
        g_dots[side][bl * 3 + 2] = sh[2][0] + sh[2][1] + sh[2][2] + sh[2][3];
    }
}

// ---------------- K3: fp16 single-pass mma GEMM, fp16 packed C output ----------------
__global__ __launch_bounds__(256, 3) void k_gemm_fp16() {
    const int side = blockIdx.z;
    unsigned* __restrict__ Cm = reinterpret_cast<unsigned*>(g_C[side]);

    extern __shared__ __align__(16) unsigned char smbuf[];   // 4 x 9216

    const int tid = threadIdx.x;
    const int lane = tid & 31, wid = tid >> 5;
    const int wm = wid >> 1, wn = wid & 1;
    const int n0 = blockIdx.x * 64;
    const int m0 = blockIdx.y * 128;

    const unsigned smem0 = s2u(&smbuf[0]);

    const int arow = tid >> 1, ahalf = tid & 1;
    const char* gA = (const char*)&g_A[side][((size_t)(m0 + arow)) * KP + ahalf * 8];
    const unsigned sA = smem0 + arow * 48 + ahalf * 16;
    const int brow = tid >> 1;
    const char* gB = (const char*)&g_W[side][((size_t)(n0 + (brow & 63))) * KP + ahalf * 8];
    const unsigned sB = smem0 + 6144u + (brow & 63) * 48 + ahalf * 16;
    const bool hasB = tid < 128;

    float acc[2][4][4];
#pragma unroll
    for (int i = 0; i < 2; i++)
#pragma unroll
        for (int j = 0; j < 4; j++)
#pragma unroll
            for (int q = 0; q < 4; q++) acc[i][j][q] = 0.f;

#pragma unroll
    for (int s = 0; s < 3; s++) {
        cp16(sA + s * STG_G, gA + s * 32);
        if (hasB) cp16(sB + s * STG_G, gB + s * 32);
        cp_commit();
    }

    const int l4 = lane & 7, g4 = lane >> 3;
    unsigned aoff[2];
#pragma unroll
    for (int mt = 0; mt < 2; mt++) {
        int rowm = wm * 32 + mt * 16 + (g4 & 1) * 8 + l4;
        aoff[mt] = smem0 + rowm * 48 + (g4 >> 1) * 16;
    }
    unsigned boff[2];
#pragma unroll
    for (int ntp = 0; ntp < 2; ntp++) {
        int rown = wn * 32 + ntp * 16 + (g4 >> 1) * 8 + l4;
        boff[ntp] = smem0 + 6144u + rown * 48 + (g4 & 1) * 16;
    }

    for (int it = 0; it < NK; it++) {
        const unsigned sbase = (unsigned)(it & 3) * STG_G;
        if (it < NK - 3) cp_wait<2>(); else cp_wait<0>();
        __syncthreads();

        if (it + 3 < NK) {
            const unsigned nb = (unsigned)((it + 3) & 3) * STG_G;
            cp16(sA + nb, gA + (it + 3) * 32);
            if (hasB) cp16(sB + nb, gB + (it + 3) * 32);
            cp_commit();
        }

        unsigned a[2][4], b[2][4];
#pragma unroll
        for (int mt = 0; mt < 2; mt++)
            ldsm4(a[mt][0], a[mt][1], a[mt][2], a[mt][3], aoff[mt] + sbase);
#pragma unroll
        for (int ntp = 0; ntp < 2; ntp++)
            ldsm4(b[ntp][0], b[ntp][1], b[ntp][2], b[ntp][3], boff[ntp] + sbase);
#pragma unroll
        for (int mt = 0; mt < 2; mt++)
#pragma unroll
            for (int nt = 0; nt < 4; nt++)
                mma_fp16(acc[mt][nt], a[mt], &b[nt >> 1][(nt & 1) * 2]);
    }

    // epilogue: pack acc pairs (c, c+1) into one u32 fp16x2 store
#pragma unroll
    for (int mt = 0; mt < 2; mt++) {
        int r = m0 + wm * 32 + mt * 16 + (lane >> 2);
#pragma unroll
        for (int nt = 0; nt < 4; nt++) {
            int c = n0 + wn * 32 + nt * 8 + 2 * (lane & 3);   // always even
            if (c < 300) {
                Cm[((size_t)r * 300 + c) >> 1]       = packh(acc[mt][nt][0], acc[mt][nt][1]);
                Cm[((size_t)(r + 8) * 300 + c) >> 1] = packh(acc[mt][nt][2], acc[mt][nt][3]);
            }
        }
    }
}

// ---------------- K4: combine (gate inline) -> utf fp16, norms, zero att --------------
__global__ __launch_bounds__(256) void k_comb(const float* __restrict__ udb,
                                              const float* __restrict__ idb,
                                              const float* __restrict__ wcb) {
    const int side = blockIdx.z;
    const int b = blockIdx.y;
    const int lbase = blockIdx.x * 32;
    const float* bias = side ? idb : udb;
    const __half2* C2 = reinterpret_cast<const __half2*>(g_C[side]) + (size_t)b * Lsz * 150;
    const float* dots = g_dots[side] + (size_t)b * Lsz * 3;
    __half* utf = g_utf[side] + (size_t)b * Lsz * KA;

    __shared__ float sgv[34];
    const float wb = wcb[0];
    if (threadIdx.x < 34) {
        int l = lbase - 1 + threadIdx.x;
        float gv = 0.f;
        if (l >= 0 && l < Lsz) {
            float g = dots[l * 3 + 1] + wb;
            if (l >= 1)        g += dots[(l - 1) * 3 + 0];
            if (l <= Lsz - 2)  g += dots[(l + 1) * 3 + 2];
            gv = 1.f / (1.f + __expf(-g));
        }
        sgv[threadIdx.x] = gv;
    }
    __syncthreads();

    const int warp = threadIdx.x >> 5, lane = threadIdx.x & 31;
#pragma unroll
    for (int po = 0; po < 4; po++) {
        const int lo = po * 8 + warp;
        const int l = lbase + lo;
        if (l >= Lsz) break;
        const float gm = sgv[lo];
        const float gc = sgv[lo + 1];
        const float gp = sgv[lo + 2];
        unsigned* urow = reinterpret_cast<unsigned*>(utf + (size_t)l * KA);
        float nr = 0.f;
#pragma unroll
        for (int half = 0; half < 2; half++) {
            const int f0 = half * 64 + 2 * lane;   // even
            float v0 = 0.f, v1 = 0.f;
            if (f0 < Fsz) {
                float2 vc = __half22float2(C2[(size_t)l * 150 + (100 + f0) / 2]);
                v0 = bias[f0] + gc * vc.x;
                v1 = bias[f0 + 1] + gc * vc.y;
                if (l >= 1) {
                    float2 vm = __half22float2(C2[(size_t)(l - 1) * 150 + f0 / 2]);
                    v0 += gm * vm.x; v1 += gm * vm.y;
                }
                if (l < Lsz - 1) {
                    float2 vp = __half22float2(C2[(size_t)(l + 1) * 150 + (200 + f0) / 2]);
                    v0 += gp * vp.x; v1 += gp * vp.y;
                }
            }
            __half h0 = __float2half(v0);
            __half h1 = __float2half(v1);
            if (f0 < KA)
                urow[half * 32 + lane] =
                    (unsigned)__half_as_ushort(h0) | ((unsigned)__half_as_ushort(h1) << 16);
            float g0 = __half2float(h0), g1 = __half2float(h1);
            nr += g0 * g0 + g1 * g1;
        }
        nr = warpSum(nr);
        if (lane == 0) {
            g_nrm[side][b * Lsz + l] = nr;
            g_att[side][b * Lsz + l] = 0.f;
        }
    }
}

// ---------------- K5: fp16 single-pass tensor-core pairwise attention ----------------
__global__ __launch_bounds__(256, 4) void k_att_tc() {
    extern __shared__ __align__(16) unsigned char sm[];
    __shared__ float rsum[64], csum[64];
    const int b = blockIdx.z;
    const int l0 = blockIdx.x * 64, m0 = blockIdx.y * 64;
    const int tid = threadIdx.x;
    const int lane = tid & 31, wid = tid >> 5;
    const int wm2 = wid >> 2, wn2 = wid & 3;
    const unsigned sbase = s2u(&sm[0]);

    if (tid < 64) { rsum[tid] = 0.f; csum[tid] = 0.f; }

    for (int i = tid; i < 2 * 64 * 14; i += 256) {
        int arr = i / 896;
        int rem = i - arr * 896;
        int r = rem / 14, c = rem - r * 14;
        int row = (arr ? m0 : l0) + r;
        bool valid = row < Lsz;
        int srow = valid ? row : 0;
        const __half* src = g_utf[arr] + ((size_t)(b * Lsz + srow)) * KA + c * 8;
        cp16z(sbase + arr * 15360 + r * 240 + c * 16, src, valid);
    }
    cp_commit();
    cp_wait<0>();
    __syncthreads();

    const int l4 = lane & 7, g4 = lane >> 3;
    unsigned aoff[2];
#pragma unroll
    for (int mt = 0; mt < 2; mt++) {
        int rowm = wm2 * 32 + mt * 16 + (g4 & 1) * 8 + l4;
        int koff = (g4 >> 1) * 8;
        aoff[mt] = sbase + (rowm * 120 + koff) * 2;
    }
    unsigned boffv;
    {
        int rown = wn2 * 16 + (g4 >> 1) * 8 + l4;
        int koff = (g4 & 1) * 8;
        boffv = sbase + 15360u + (rown * 120 + koff) * 2;
    }

    float acc[2][2][4];
#pragma unroll
    for (int i = 0; i < 2; i++)
#pragma unroll
        for (int j = 0; j < 2; j++)
#pragma unroll
            for (int q = 0; q < 4; q++) acc[i][j][q] = 0.f;

#pragma unroll
    for (int ck = 0; ck < 7; ck++) {
        const unsigned kb = ck * 32;
        unsigned a[2][4], bfr[4];
#pragma unroll
        for (int mt = 0; mt < 2; mt++)
            ldsm4(a[mt][0], a[mt][1], a[mt][2], a[mt][3], aoff[mt] + kb);
        ldsm4(bfr[0], bfr[1], bfr[2], bfr[3], boffv + kb);
#pragma unroll
        for (int mt = 0; mt < 2; mt++)
#pragma unroll
            for (int nt = 0; nt < 2; nt++)
                mma_fp16(acc[mt][nt], a[mt], &bfr[nt * 2]);
    }

    float nu[2][2], nv[2][2];
#pragma unroll
    for (int mt = 0; mt < 2; mt++)
#pragma unroll
        for (int h = 0; h < 2; h++) {
            int l = l0 + wm2 * 32 + mt * 16 + h * 8 + (lane >> 2);
            nu[mt][h] = (l < Lsz) ? g_nrm[0][b * Lsz + l] : 0.f;
        }
#pragma unroll
    for (int nt = 0; nt < 2; nt++)
#pragma unroll
        for (int cc = 0; cc < 2; cc++) {
            int m = m0 + wn2 * 16 + nt * 8 + 2 * (lane & 3) + cc;
            nv[nt][cc] = (m < Lsz) ? g_nrm[1][b * Lsz + m] : 0.f;
        }

    float rsv[4] = {0, 0, 0, 0}, csv[4] = {0, 0, 0, 0};
#pragma unroll
    for (int mt = 0; mt < 2; mt++)
#pragma unroll
        for (int nt = 0; nt < 2; nt++)
#pragma unroll
            for (int q = 0; q < 4; q++) {
                int h = q >> 1, cc = q & 1;
                int l = l0 + wm2 * 32 + mt * 16 + h * 8 + (lane >> 2);
                int m = m0 + wn2 * 16 + nt * 8 + 2 * (lane & 3) + cc;
                if (l < Lsz && m < Lsz) {
                    float sq = nu[mt][h] + nv[nt][cc] - 2.f * acc[mt][nt][q];
                    float a = 1.f / (1.f + sqrtf(fmaxf(sq, 1e-12f)));
                    rsv[mt * 2 + h] += a;
                    csv[nt * 2 + cc] += a;
                }
            }
#pragma unroll
    for (int q = 0; q < 4; q++) {
        atomicAdd(&rsum[wm2 * 32 + (q >> 1) * 16 + (q & 1) * 8 + (lane >> 2)], rsv[q]);
        atomicAdd(&csum[wn2 * 16 + (q >> 1) * 8 + 2 * (lane & 3) + (q & 1)], csv[q]);
    }
    __syncthreads();
    if (tid < 64) {
        if (l0 + tid < Lsz) atomicAdd(&g_att[0][b * Lsz + l0 + tid], rsum[tid]);
        if (m0 + tid < Lsz) atomicAdd(&g_att[1][b * Lsz + m0 + tid], csum[tid]);
    }
}

// ---------------- K6: head via closed-form pooling (4-way l-split) -------------------
// s0 = 3P - p0 - p497 - 2p498 - 3p499 ; s1 = 3P - 2p0 - p1 - p498 - 2p499 ;
// s2 = 3P - 3p0 - 2p1 - p2 - p499 ; where p[l] = ut[l]*att[l], P = sum_l p[l].
__global__ __launch_bounds__(512) void k_head(
                       const float* __restrict__ uacw, const float* __restrict__ uacb,
                       const float* __restrict__ iacw, const float* __restrict__ iacb,
                       const float* __restrict__ ufw,  const float* __restrict__ ufb,
                       const float* __restrict__ ifw,  const float* __restrict__ ifb,
                       const int* __restrict__ uids,   const int* __restrict__ iids,
                       const float* __restrict__ uide, const float* __restrict__ iide,
                       float* __restrict__ out) {
    int b = blockIdx.x;
    int side = blockIdx.y;
    const __half* ut = g_utf[side] + (size_t)b * Lsz * KA;
    const float* att = g_att[side] + b * Lsz;
    const float* acw = side ? iacw : uacw;
    const float* acb = side ? iacb : uacb;
    const float* fw  = side ? ifw : ufw;
    const float* fb  = side ? ifb : ufb;
    __shared__ float satt[Lsz];
    __shared__ float sp[4][KA];
    __shared__ float sedge[6][KA];
    __shared__ float S[3][Fsz];
    __shared__ float am[Fsz];
    const int tid = threadIdx.x;

    for (int i = tid; i < Lsz; i += 512) satt[i] = att[i];
    __syncthreads();

    const int g = tid >> 7, tg = tid & 127;
    if (tg < KA) {
        float acc = 0.f;
        const int la = g * 125, lb2 = la + 125;
        for (int l = la; l < lb2; l++) {
            float p = __half2float(ut[(size_t)l * KA + tg]) * satt[l];
            acc += p;
            if (l < 3) sedge[l][tg] = p;
            else if (l >= 497) sedge[l - 494][tg] = p;   // 497->3, 498->4, 499->5
        }
        sp[g][tg] = acc;
    }
    __syncthreads();
    if (tid < Fsz) {
        float P3 = 3.f * (sp[0][tid] + sp[1][tid] + sp[2][tid] + sp[3][tid]);
        float p0 = sedge[0][tid], p1 = sedge[1][tid], p2 = sedge[2][tid];
        float q2 = sedge[3][tid], q1 = sedge[4][tid], q0 = sedge[5][tid];  // p497,p498,p499
        S[0][tid] = P3 -       p0              -       q2 - 2.f * q1 - 3.f * q0;
        S[1][tid] = P3 - 2.f * p0 -       p1              -       q1 - 2.f * q0;
        S[2][tid] = P3 - 3.f * p0 - 2.f * p1 - p2                    -       q0;
    }
    __syncthreads();
    if (tid < Fsz) {
        float a = 0.f;
#pragma unroll
        for (int k = 0; k < 3; k++)
            for (int gg = 0; gg < Fsz; gg++)
                a += S[k][gg] * acw[(tid * 3 + k) * Fsz + gg];
        am[tid] = acb[tid] + a * (1.f / (float)(Lsz - 2));
    }
    __syncthreads();
    if (tid < IDs) {
        float o = fb[tid];
        for (int f = 0; f < Fsz; f++) o += am[f] * fw[tid * Fsz + f];
        o = fmaxf(o, 0.f);
        int base = side ? (Bsz * 2 * IDs) : 0;
        out[base + (b * 2 + 0) * IDs + tid] = o;
    }
    if (tid >= 64 && tid < 64 + IDs) {
        int i = tid - 64;
        if (side == 0) {
            out[(b * 2 + 1) * IDs + i] = iide[(size_t)iids[b] * IDs + i];
        } else {
            out[Bsz * 2 * IDs + (b * 2 + 1) * IDs + i] = uide[(size_t)uids[b] * IDs + i];
        }
    }
}

// ---------------- launch ----------------
extern "C" void kernel_launch(void* const* d_in, const int* in_sizes, int n_in,
                              void* d_out, int out_size) {
    const int*   uids = (const int*)d_in[0];
    const int*   iids = (const int*)d_in[1];
    const int*   udoc = (const int*)d_in[2];
    const int*   idoc = (const int*)d_in[3];
    const float* uemb = (const float*)d_in[4];
    const float* iemb = (const float*)d_in[5];
    const float* wcw  = (const float*)d_in[6];
    const float* wcb  = (const float*)d_in[7];
    const float* udcw = (const float*)d_in[8];
    const float* udcb = (const float*)d_in[9];
    const float* idcw = (const float*)d_in[10];
    const float* idcb = (const float*)d_in[11];
    const float* uacw = (const float*)d_in[12];
    const float* uacb = (const float*)d_in[13];
    const float* iacw = (const float*)d_in[14];
    const float* iacb = (const float*)d_in[15];
    const float* ufw  = (const float*)d_in[16];
    const float* ufb  = (const float*)d_in[17];
    const float* ifw  = (const float*)d_in[18];
    const float* ifb  = (const float*)d_in[19];
    const float* uide = (const float*)d_in[20];
    const float* iide = (const float*)d_in[21];
    float* out = (float*)d_out;

    cudaFuncSetAttribute(k_gemm_fp16, cudaFuncAttributeMaxDynamicSharedMemorySize, 4 * (int)STG_G);
    cudaFuncSetAttribute(k_att_tc,    cudaFuncAttributeMaxDynamicSharedMemorySize, 2 * 15360);

    k_prep<<<(2 * KP * KP + 255) / 256, 256>>>(udcw, idcw);
    dim3 gBL(BL, 2);
    k_gather<<<gBL, 128>>>(udoc, idoc, uemb, iemb, wcw);
    k_gemm_fp16<<<dim3(5, 250, 2), 256, 4 * STG_G>>>();
    k_comb<<<dim3(16, Bsz, 2), 256>>>(udcb, idcb, wcb);
    k_att_tc<<<dim3(8, 8, Bsz), 256, 2 * 15360>>>();
    k_head<<<dim3(Bsz, 2), 512>>>(uacw, uacb, iacw, iacb, ufw, ufb, ifw, ifb,
                                  uids, iids, uide, iide, out);
}